// round 6
// baseline (speedup 1.0000x reference)
#include <cuda_runtime.h>
#include <cuda_bf16.h>
#include <math.h>
#include <stdint.h>

// ---------------- Problem constants ----------------
#define BB    4
#define TT    1024
#define NTOK  (BB*TT)
#define DD    768
#define HH    12
#define HD    64
#define LL    6
#define VV    32000
#define DFF   3072
#define DQKV  2304
#define EPS   1e-5f

// ---------------- Static device buffers ------------
__device__ float g_h   [NTOK * DD];     // residual stream (fp32)
__device__ float g_qkv [NTOK * DQKV];   // qkv projections (fp32)
__device__ __nv_bfloat16 g_xh[NTOK*DD],  g_xl[NTOK*DD];    // LN out hi/lo
__device__ __nv_bfloat16 g_ah[NTOK*DD],  g_al[NTOK*DD];    // attn out hi/lo
__device__ __nv_bfloat16 g_fh[NTOK*DFF], g_fl[NTOK*DFF];   // relu out hi/lo
// bf16 hi/lo weight copies
__device__ __nv_bfloat16 w_qkvh[LL*DQKV*DD], w_qkvl[LL*DQKV*DD];
__device__ __nv_bfloat16 w_fch [LL*DD*DD],   w_fcl [LL*DD*DD];
__device__ __nv_bfloat16 w_f1h [LL*DFF*DD],  w_f1l [LL*DFF*DD];
__device__ __nv_bfloat16 w_f2h [LL*DD*DFF],  w_f2l [LL*DD*DFF];
__device__ __nv_bfloat16 w_oh  [VV*DD],      w_ol  [VV*DD];

// ---------------- PTX helpers (arch-generic only) ---
__device__ __forceinline__ uint32_t smem_to_u32(const void* p) {
    uint32_t a;
    asm("{ .reg .u64 t; cvta.to.shared.u64 t, %1; cvt.u32.u64 %0, t; }"
        : "=r"(a) : "l"(p));
    return a;
}
#define CP_ASYNC16(dst, src) \
    asm volatile("cp.async.cg.shared.global [%0], [%1], 16;" :: "r"(dst), "l"(src))
#define CP_COMMIT asm volatile("cp.async.commit_group;" ::: "memory")
#define CP_WAIT1  asm volatile("cp.async.wait_group 1;" ::: "memory")
#define CP_WAIT0  asm volatile("cp.async.wait_group 0;" ::: "memory")

__device__ __forceinline__ void ldsm4(uint32_t* r, uint32_t addr) {
    asm volatile("ldmatrix.sync.aligned.m8n8.x4.shared.b16 {%0,%1,%2,%3}, [%4];"
        : "=r"(r[0]), "=r"(r[1]), "=r"(r[2]), "=r"(r[3]) : "r"(addr));
}
__device__ __forceinline__ void ldsm2(uint32_t* r, uint32_t addr) {
    asm volatile("ldmatrix.sync.aligned.m8n8.x2.shared.b16 {%0,%1}, [%2];"
        : "=r"(r[0]), "=r"(r[1]) : "r"(addr));
}
__device__ __forceinline__ void mma_bf16(float* d, const uint32_t* a, const uint32_t* b) {
    asm volatile("mma.sync.aligned.m16n8k16.row.col.f32.bf16.bf16.f32 "
        "{%0,%1,%2,%3}, {%4,%5,%6,%7}, {%8,%9}, {%0,%1,%2,%3};"
        : "+f"(d[0]), "+f"(d[1]), "+f"(d[2]), "+f"(d[3])
        : "r"(a[0]), "r"(a[1]), "r"(a[2]), "r"(a[3]), "r"(b[0]), "r"(b[1]));
}

// fast exp on FMA pipe (no MUFU), deg-7, rel err ~1e-6 for x <= 0.
__device__ __forceinline__ float fexp(float x) {
    float t = x * 1.4426950408889634f;           // x / ln2
    t = fmaxf(t, -126.0f);
    float n = floorf(t);
    float f = (t - n) * 0.6931471805599453f;     // f in [0, ln2)
    float p = 1.98412698e-4f;
    p = fmaf(p, f, 1.38888889e-3f);
    p = fmaf(p, f, 8.33333333e-3f);
    p = fmaf(p, f, 4.16666667e-2f);
    p = fmaf(p, f, 1.66666667e-1f);
    p = fmaf(p, f, 5.0e-1f);
    p = fmaf(p, f, 1.0f);
    p = fmaf(p, f, 1.0f);
    float sc = __int_as_float(((int)n + 127) << 23);
    return p * sc;
}

// ---------------- Embedding ------------------------
__global__ void embed_kernel(const int* __restrict__ x,
                             const float* __restrict__ tok_emb,
                             const float* __restrict__ pos_emb) {
    int row = blockIdx.x;
    int t   = row % TT;
    int id  = x[row];
    const float* te = tok_emb + (size_t)id * DD;
    const float* pe = pos_emb + (size_t)t  * DD;
    float* out = g_h + (size_t)row * DD;
    for (int i = threadIdx.x; i < DD; i += blockDim.x)
        out[i] = te[i] + pe[i];
}

// ---------------- fp32 -> bf16 hi/lo split ---------
__global__ void cvt_kernel(const float* __restrict__ s,
                           __nv_bfloat16* __restrict__ hi,
                           __nv_bfloat16* __restrict__ lo, int n4) {
    int i = blockIdx.x * blockDim.x + threadIdx.x;
    int stride = gridDim.x * blockDim.x;
    for (; i < n4; i += stride) {
        float4 v = ((const float4*)s)[i];
        __nv_bfloat16 h0 = __float2bfloat16(v.x);
        __nv_bfloat16 h1 = __float2bfloat16(v.y);
        __nv_bfloat16 h2 = __float2bfloat16(v.z);
        __nv_bfloat16 h3 = __float2bfloat16(v.w);
        __nv_bfloat16 l0 = __float2bfloat16(v.x - __bfloat162float(h0));
        __nv_bfloat16 l1 = __float2bfloat16(v.y - __bfloat162float(h1));
        __nv_bfloat16 l2 = __float2bfloat16(v.z - __bfloat162float(h2));
        __nv_bfloat16 l3 = __float2bfloat16(v.w - __bfloat162float(h3));
        __nv_bfloat162* ph = (__nv_bfloat162*)hi + i*2;
        __nv_bfloat162* pl = (__nv_bfloat162*)lo + i*2;
        ph[0] = __nv_bfloat162(h0, h1); ph[1] = __nv_bfloat162(h2, h3);
        pl[0] = __nv_bfloat162(l0, l1); pl[1] = __nv_bfloat162(l2, l3);
    }
}

// ---------------- LayerNorm -> bf16 hi/lo ----------
__device__ __forceinline__ float block_reduce_sum(float v, float* red) {
    int lane = threadIdx.x & 31, wid = threadIdx.x >> 5;
    #pragma unroll
    for (int o = 16; o > 0; o >>= 1) v += __shfl_xor_sync(0xffffffffu, v, o);
    if (lane == 0) red[wid] = v;
    __syncthreads();
    if (wid == 0) {
        float w = (lane < (blockDim.x >> 5)) ? red[lane] : 0.f;
        #pragma unroll
        for (int o = 4; o > 0; o >>= 1) w += __shfl_xor_sync(0xffffffffu, w, o);
        if (lane == 0) red[0] = w;
    }
    __syncthreads();
    float r = red[0];
    __syncthreads();
    return r;
}

__global__ void ln_kernel(const float* __restrict__ xin,
                          const float* __restrict__ sc,
                          const float* __restrict__ bi,
                          __nv_bfloat16* __restrict__ yh,
                          __nv_bfloat16* __restrict__ yl) {
    __shared__ float red[32];
    int row = blockIdx.x;
    const float* xr = xin + (size_t)row * DD;
    float xv[3];
    float s = 0.f;
    #pragma unroll
    for (int i = 0; i < 3; i++) { xv[i] = xr[threadIdx.x + i*256]; s += xv[i]; }
    float mean = block_reduce_sum(s, red) * (1.0f / DD);
    float vs = 0.f;
    #pragma unroll
    for (int i = 0; i < 3; i++) { float d = xv[i] - mean; vs += d * d; }
    float var = block_reduce_sum(vs, red) * (1.0f / DD);
    float rstd = rsqrtf(var + EPS);
    #pragma unroll
    for (int i = 0; i < 3; i++) {
        int c = threadIdx.x + i*256;
        float v = (xv[i] - mean) * rstd * sc[c] + bi[c];
        __nv_bfloat16 h = __float2bfloat16(v);
        yh[(size_t)row*DD + c] = h;
        yl[(size_t)row*DD + c] = __float2bfloat16(v - __bfloat162float(h));
    }
}

// =============== 128x128 HMMA GEMM (validated) =============================
#define KC         64
#define TILE_B     16384
#define STG_B      (4*TILE_B)
#define GEMM_SMEM  (2*STG_B)

template<int OP>
__global__ __launch_bounds__(256, 1)
void mm_kernel(const __nv_bfloat16* __restrict__ Ah, const __nv_bfloat16* __restrict__ Al,
               const __nv_bfloat16* __restrict__ Wh, const __nv_bfloat16* __restrict__ Wl,
               const float* __restrict__ bias, float* __restrict__ C,
               __nv_bfloat16* __restrict__ Oh, __nv_bfloat16* __restrict__ Ol,
               int N, int K) {
    extern __shared__ char smem[];
    const uint32_t sb = smem_to_u32(smem);
    int tid = threadIdx.x, lane = tid & 31, warp = tid >> 5;
    int wm = warp >> 2;
    int wn = warp & 3;
    int bm = blockIdx.x * 128, bn = blockIdx.y * 128;

    float acc[4][4][4];
    #pragma unroll
    for (int i = 0; i < 4; i++)
        #pragma unroll
        for (int j = 0; j < 4; j++)
            #pragma unroll
            for (int k = 0; k < 4; k++) acc[i][j][k] = 0.f;

    int crow = tid >> 1;
    int cch0 = (tid & 1) * 4;
    const __nv_bfloat16* gA_h = Ah + (size_t)(bm + crow) * K + cch0 * 8;
    const __nv_bfloat16* gA_l = Al + (size_t)(bm + crow) * K + cch0 * 8;
    const __nv_bfloat16* gW_h = Wh + (size_t)(bn + crow) * K + cch0 * 8;
    const __nv_bfloat16* gW_l = Wl + (size_t)(bn + crow) * K + cch0 * 8;
    uint32_t srow = (uint32_t)crow * 128;
    int rsw = crow & 7;

    int mat = lane >> 3, r8 = lane & 7;
    int a_kh = mat >> 1;
    uint32_t arowb[4]; int aswz[4];
    #pragma unroll
    for (int ti = 0; ti < 4; ti++) {
        int row = wm*64 + ti*16 + (mat & 1)*8 + r8;
        arowb[ti] = (uint32_t)row * 128;
        aswz[ti]  = row & 7;
    }
    int bl15 = lane & 15;
    int b_kh = bl15 >> 3;
    uint32_t browb[4]; int bswz[4];
    #pragma unroll
    for (int ni = 0; ni < 4; ni++) {
        int row = wn*32 + ni*8 + (bl15 & 7);
        browb[ni] = (uint32_t)row * 128;
        bswz[ni]  = row & 7;
    }

    const int nch = K / KC;
    {
        uint32_t st = sb;
        #pragma unroll
        for (int i = 0; i < 4; i++) {
            int c = cch0 + i;
            uint32_t soff = srow + (uint32_t)((c ^ rsw) << 4);
            CP_ASYNC16(st + soff,            gA_h + i*8);
            CP_ASYNC16(st + TILE_B + soff,   gA_l + i*8);
            CP_ASYNC16(st + 2*TILE_B + soff, gW_h + i*8);
            CP_ASYNC16(st + 3*TILE_B + soff, gW_l + i*8);
        }
        CP_COMMIT;
    }

    for (int ch = 0; ch < nch; ch++) {
        if (ch + 1 < nch) {
            uint32_t st = sb + ((ch + 1) & 1) * STG_B;
            int k0 = (ch + 1) * KC;
            #pragma unroll
            for (int i = 0; i < 4; i++) {
                int c = cch0 + i;
                uint32_t soff = srow + (uint32_t)((c ^ rsw) << 4);
                CP_ASYNC16(st + soff,            gA_h + k0 + i*8);
                CP_ASYNC16(st + TILE_B + soff,   gA_l + k0 + i*8);
                CP_ASYNC16(st + 2*TILE_B + soff, gW_h + k0 + i*8);
                CP_ASYNC16(st + 3*TILE_B + soff, gW_l + k0 + i*8);
            }
            CP_COMMIT;
            CP_WAIT1;
        } else {
            CP_WAIT0;
        }
        __syncthreads();

        uint32_t stA = sb + (ch & 1) * STG_B;
        uint32_t stW = stA + 2*TILE_B;
        #pragma unroll
        for (int ks = 0; ks < 4; ks++) {
            uint32_t ahf[4][4], alf[4][4];
            #pragma unroll
            for (int ti = 0; ti < 4; ti++) {
                uint32_t off = arowb[ti] + (uint32_t)((((ks << 1) | a_kh) ^ aswz[ti]) << 4);
                ldsm4(ahf[ti], stA + off);
                ldsm4(alf[ti], stA + TILE_B + off);
            }
            uint32_t bhf[4][2], blf[4][2];
            #pragma unroll
            for (int ni = 0; ni < 4; ni++) {
                uint32_t off = browb[ni] + (uint32_t)((((ks << 1) | b_kh) ^ bswz[ni]) << 4);
                ldsm2(bhf[ni], stW + off);
                ldsm2(blf[ni], stW + TILE_B + off);
            }
            #pragma unroll
            for (int ti = 0; ti < 4; ti++)
                #pragma unroll
                for (int ni = 0; ni < 4; ni++) {
                    mma_bf16(acc[ti][ni], ahf[ti], bhf[ni]);
                    mma_bf16(acc[ti][ni], ahf[ti], blf[ni]);
                    mma_bf16(acc[ti][ni], alf[ti], bhf[ni]);
                }
        }
        __syncthreads();
    }

    int lr = lane >> 2, lc = (lane & 3) * 2;
    #pragma unroll
    for (int ti = 0; ti < 4; ti++) {
        #pragma unroll
        for (int ni = 0; ni < 4; ni++) {
            int grow = bm + wm*64 + ti*16 + lr;
            int gcol = bn + wn*32 + ni*8 + lc;
            #pragma unroll
            for (int half = 0; half < 2; half++) {
                int r = grow + half*8;
                size_t off = (size_t)r * N + gcol;
                float v0 = acc[ti][ni][half*2 + 0];
                float v1 = acc[ti][ni][half*2 + 1];
                if (OP == 0) {
                    *(float2*)&C[off] = make_float2(v0, v1);
                } else if (OP == 1) {
                    *(float2*)&C[off] = make_float2(v0 + bias[gcol], v1 + bias[gcol+1]);
                } else if (OP == 2) {
                    float2 hcur = *(float2*)&C[off];
                    *(float2*)&C[off] = make_float2(v0 + bias[gcol]   + hcur.x,
                                                    v1 + bias[gcol+1] + hcur.y);
                } else {
                    float f0 = fmaxf(v0 + bias[gcol],   0.f);
                    float f1 = fmaxf(v1 + bias[gcol+1], 0.f);
                    __nv_bfloat16 h0 = __float2bfloat16(f0);
                    __nv_bfloat16 h1 = __float2bfloat16(f1);
                    *(__nv_bfloat162*)&Oh[off] = __nv_bfloat162(h0, h1);
                    __nv_bfloat16 l0 = __float2bfloat16(f0 - __bfloat162float(h0));
                    __nv_bfloat16 l1 = __float2bfloat16(f1 - __bfloat162float(h1));
                    *(__nv_bfloat162*)&Ol[off] = __nv_bfloat162(l0, l1);
                }
            }
        }
    }
}

// =============== 256x128 HMMA GEMM (high arithmetic intensity) =============
#define B_AH   0
#define B_AL   32768
#define B_WH   65536
#define B_WL   81920
#define STG2_B 98304
#define GEMM2_SMEM (2*STG2_B)

template<int OP>
__global__ __launch_bounds__(256, 1)
void mm_big(const __nv_bfloat16* __restrict__ Ah, const __nv_bfloat16* __restrict__ Al,
            const __nv_bfloat16* __restrict__ Wh, const __nv_bfloat16* __restrict__ Wl,
            const float* __restrict__ bias, float* __restrict__ C,
            __nv_bfloat16* __restrict__ Oh, __nv_bfloat16* __restrict__ Ol,
            int N, int K) {
    extern __shared__ char smem[];
    const uint32_t sb = smem_to_u32(smem);
    int tid = threadIdx.x, lane = tid & 31, warp = tid >> 5;
    int wm = warp >> 1;          // 0..3 -> 64 rows each
    int wn = warp & 1;           // 0..1 -> 64 cols each
    int bm = blockIdx.x * 256, bn = blockIdx.y * 128;

    float acc[4][8][4];
    #pragma unroll
    for (int i = 0; i < 4; i++)
        #pragma unroll
        for (int j = 0; j < 8; j++)
            #pragma unroll
            for (int k = 0; k < 4; k++) acc[i][j][k] = 0.f;

    int arow = tid;
    const __nv_bfloat16* gA_h = Ah + (size_t)(bm + arow) * K;
    const __nv_bfloat16* gA_l = Al + (size_t)(bm + arow) * K;
    uint32_t asrow = (uint32_t)arow * 128;
    int arsw = arow & 7;
    int wrow = tid >> 1;
    int wc0  = (tid & 1) * 4;
    const __nv_bfloat16* gW_h = Wh + (size_t)(bn + wrow) * K + wc0 * 8;
    const __nv_bfloat16* gW_l = Wl + (size_t)(bn + wrow) * K + wc0 * 8;
    uint32_t wsrow = (uint32_t)wrow * 128;
    int wrsw = wrow & 7;

    int mat = lane >> 3, r8 = lane & 7;
    int a_kh = mat >> 1;
    uint32_t arowb[4]; int aswz[4];
    #pragma unroll
    for (int ti = 0; ti < 4; ti++) {
        int row = wm*64 + ti*16 + (mat & 1)*8 + r8;
        arowb[ti] = (uint32_t)row * 128;
        aswz[ti]  = row & 7;
    }
    int b_nr8 = ((lane >> 4) & 1) * 8 + (lane & 7);
    int b_kh  = (lane >> 3) & 1;
    uint32_t browb[4]; int bswz[4];
    #pragma unroll
    for (int nj = 0; nj < 4; nj++) {
        int row = wn*64 + nj*16 + b_nr8;
        browb[nj] = (uint32_t)row * 128;
        bswz[nj]  = row & 7;
    }

    const int nch = K / KC;
    {
        uint32_t st = sb;
        #pragma unroll
        for (int c = 0; c < 8; c++) {
            uint32_t soff = asrow + (uint32_t)((c ^ arsw) << 4);
            CP_ASYNC16(st + B_AH + soff, gA_h + c*8);
            CP_ASYNC16(st + B_AL + soff, gA_l + c*8);
        }
        #pragma unroll
        for (int i = 0; i < 4; i++) {
            int c = wc0 + i;
            uint32_t soff = wsrow + (uint32_t)((c ^ wrsw) << 4);
            CP_ASYNC16(st + B_WH + soff, gW_h + i*8);
            CP_ASYNC16(st + B_WL + soff, gW_l + i*8);
        }
        CP_COMMIT;
    }

    for (int ch = 0; ch < nch; ch++) {
        if (ch + 1 < nch) {
            uint32_t st = sb + ((ch + 1) & 1) * STG2_B;
            int k0 = (ch + 1) * KC;
            #pragma unroll
            for (int c = 0; c < 8; c++) {
                uint32_t soff = asrow + (uint32_t)((c ^ arsw) << 4);
                CP_ASYNC16(st + B_AH + soff, gA_h + k0 + c*8);
                CP_ASYNC16(st + B_AL + soff, gA_l + k0 + c*8);
            }
            #pragma unroll
            for (int i = 0; i < 4; i++) {
                int c = wc0 + i;
                uint32_t soff = wsrow + (uint32_t)((c ^ wrsw) << 4);
                CP_ASYNC16(st + B_WH + soff, gW_h + k0 + i*8);
                CP_ASYNC16(st + B_WL + soff, gW_l + k0 + i*8);
            }
            CP_COMMIT;
            CP_WAIT1;
        } else {
            CP_WAIT0;
        }
        __syncthreads();

        uint32_t stg = sb + (ch & 1) * STG2_B;
        #pragma unroll
        for (int ks = 0; ks < 4; ks++) {
            uint32_t ahf[4][4], alf[4][4];
            #pragma unroll
            for (int ti = 0; ti < 4; ti++) {
                uint32_t off = arowb[ti] + (uint32_t)((((ks << 1) | a_kh) ^ aswz[ti]) << 4);
                ldsm4(ahf[ti], stg + B_AH + off);
                ldsm4(alf[ti], stg + B_AL + off);
            }
            uint32_t bhf[8][2], blf[8][2];
            #pragma unroll
            for (int nj = 0; nj < 4; nj++) {
                uint32_t off = browb[nj] + (uint32_t)((((ks << 1) | b_kh) ^ bswz[nj]) << 4);
                uint32_t t4[4];
                ldsm4(t4, stg + B_WH + off);
                bhf[nj*2][0] = t4[0]; bhf[nj*2][1] = t4[1];
                bhf[nj*2+1][0] = t4[2]; bhf[nj*2+1][1] = t4[3];
                ldsm4(t4, stg + B_WL + off);
                blf[nj*2][0] = t4[0]; blf[nj*2][1] = t4[1];
                blf[nj*2+1][0] = t4[2]; blf[nj*2+1][1] = t4[3];
            }
            #pragma unroll
            for (int ti = 0; ti < 4; ti++)
                #pragma unroll
                for (int ni = 0; ni < 8; ni++) {
                    mma_bf16(acc[ti][ni], ahf[ti], bhf[ni]);
                    mma_bf16(acc[ti][ni], ahf[ti], blf[ni]);
                    mma_bf16(acc[ti][ni], alf[ti], bhf[ni]);
                }
        }
        __syncthreads();
    }

    int lr = lane >> 2, lc = (lane & 3) * 2;
    #pragma unroll
    for (int ti = 0; ti < 4; ti++) {
        #pragma unroll
        for (int ni = 0; ni < 8; ni++) {
            int grow = bm + wm*64 + ti*16 + lr;
            int gcol = bn + wn*64 + ni*8 + lc;
            #pragma unroll
            for (int half = 0; half < 2; half++) {
                int r = grow + half*8;
                size_t off = (size_t)r * N + gcol;
                float v0 = acc[ti][ni][half*2 + 0];
                float v1 = acc[ti][ni][half*2 + 1];
                if (OP == 0) {
                    *(float2*)&C[off] = make_float2(v0, v1);
                } else if (OP == 1) {
                    *(float2*)&C[off] = make_float2(v0 + bias[gcol], v1 + bias[gcol+1]);
                } else if (OP == 2) {
                    float2 hcur = *(float2*)&C[off];
                    *(float2*)&C[off] = make_float2(v0 + bias[gcol]   + hcur.x,
                                                    v1 + bias[gcol+1] + hcur.y);
                } else {
                    float f0 = fmaxf(v0 + bias[gcol],   0.f);
                    float f1 = fmaxf(v1 + bias[gcol+1], 0.f);
                    __nv_bfloat16 h0 = __float2bfloat16(f0);
                    __nv_bfloat16 h1 = __float2bfloat16(f1);
                    *(__nv_bfloat162*)&Oh[off] = __nv_bfloat162(h0, h1);
                    __nv_bfloat16 l0 = __float2bfloat16(f0 - __bfloat162float(h0));
                    __nv_bfloat16 l1 = __float2bfloat16(f1 - __bfloat162float(h1));
                    *(__nv_bfloat162*)&Ol[off] = __nv_bfloat162(l0, l1);
                }
            }
        }
    }
}

// =============== Causal attention: 4 q/thread, 16-dim lane slice ===========
// WARP-UNIFORM inner trip count (fixes round-4 shfl deadlock); causality via
// the per-query `ok` predicate only.
__global__ __launch_bounds__(256)
void attn_kernel(const float* __restrict__ qkv,
                 __nv_bfloat16* __restrict__ oh, __nv_bfloat16* __restrict__ ol) {
    __shared__ float Ks[64][64];
    __shared__ float Vs[64][64];

    int bh = blockIdx.y;
    int b  = bh / HH, h = bh % HH;
    int tid = threadIdx.x;
    int warp = tid >> 5;
    int quad = tid >> 2, dg = tid & 3;
    int q0 = blockIdx.x * 256 + quad * 4;
    int d0 = dg * 16;
    int qwmax = blockIdx.x * 256 + warp * 32 + 31;   // warp's max query

    float4 qr[4][4];
    #pragma unroll
    for (int i = 0; i < 4; i++) {
        const float4* qp = (const float4*)(qkv + (size_t)(b*TT + q0 + i) * DQKV + h*HD + d0);
        #pragma unroll
        for (int c = 0; c < 4; c++) {
            qr[i][c] = qp[c];
            qr[i][c].x *= 0.125f; qr[i][c].y *= 0.125f;
            qr[i][c].z *= 0.125f; qr[i][c].w *= 0.125f;
        }
    }
    float4 av[4][4];
    #pragma unroll
    for (int i = 0; i < 4; i++)
        #pragma unroll
        for (int c = 0; c < 4; c++) av[i][c] = make_float4(0.f,0.f,0.f,0.f);
    float m[4], lsum[4];
    #pragma unroll
    for (int i = 0; i < 4; i++) { m[i] = -1e30f; lsum[i] = 0.f; }

    int ntile = blockIdx.x * 4 + 4;
    int lrow = tid >> 2, lseg = (tid & 3) * 4;

    for (int kt = 0; kt < ntile; kt++) {
        const float* kb = qkv + (size_t)(b*TT + kt*64) * DQKV + DD + h*HD;
        const float* vb = kb + DD;
        __syncthreads();
        {
            const float4* ksrc = (const float4*)(kb + (size_t)lrow * DQKV);
            const float4* vsrc = (const float4*)(vb + (size_t)lrow * DQKV);
            float4* kdst = (float4*)&Ks[lrow][0];
            float4* vdst = (float4*)&Vs[lrow][0];
            #pragma unroll
            for (int c = 0; c < 4; c++) {
                kdst[lseg + c] = ksrc[lseg + c];
                vdst[lseg + c] = vsrc[lseg + c];
            }
        }
        __syncthreads();

        // warp-uniform trip count
        int jm = qwmax - kt*64 + 1;
        jm = (jm > 64) ? 64 : jm;
        if (jm <= 0) continue;
        for (int j = 0; j < jm; j++) {
            const float4* kr = (const float4*)&Ks[j][d0];
            float4 k0v = kr[0], k1v = kr[1], k2v = kr[2], k3v = kr[3];
            float sp[4];
            #pragma unroll
            for (int i = 0; i < 4; i++) {
                float s;
                s  = qr[i][0].x*k0v.x + qr[i][0].y*k0v.y + qr[i][0].z*k0v.z + qr[i][0].w*k0v.w;
                s += qr[i][1].x*k1v.x + qr[i][1].y*k1v.y + qr[i][1].z*k1v.z + qr[i][1].w*k1v.w;
                s += qr[i][2].x*k2v.x + qr[i][2].y*k2v.y + qr[i][2].z*k2v.z + qr[i][2].w*k2v.w;
                s += qr[i][3].x*k3v.x + qr[i][3].y*k3v.y + qr[i][3].z*k3v.z + qr[i][3].w*k3v.w;
                sp[i] = s;
            }
            #pragma unroll
            for (int i = 0; i < 4; i++) {
                sp[i] += __shfl_xor_sync(0xffffffffu, sp[i], 1);
                sp[i] += __shfl_xor_sync(0xffffffffu, sp[i], 2);
            }
            int rel = kt*64 + j;
            float p[4];
            #pragma unroll
            for (int i = 0; i < 4; i++) {
                bool ok = (rel <= q0 + i);
                float s = sp[i];
                if (ok && s > m[i]) {
                    float corr = fexp(m[i] - s);
                    #pragma unroll
                    for (int c = 0; c < 4; c++) {
                        av[i][c].x *= corr; av[i][c].y *= corr;
                        av[i][c].z *= corr; av[i][c].w *= corr;
                    }
                    lsum[i] = lsum[i] * corr + 1.f;
                    m[i] = s;
                    p[i] = 1.f;
                } else {
                    p[i] = ok ? fexp(s - m[i]) : 0.f;
                    lsum[i] += p[i];
                }
            }
            const float4* vr = (const float4*)&Vs[j][d0];
            float4 v0v = vr[0], v1v = vr[1], v2v = vr[2], v3v = vr[3];
            #pragma unroll
            for (int i = 0; i < 4; i++) {
                float pi = p[i];
                av[i][0].x = fmaf(pi, v0v.x, av[i][0].x);
                av[i][0].y = fmaf(pi, v0v.y, av[i][0].y);
                av[i][0].z = fmaf(pi, v0v.z, av[i][0].z);
                av[i][0].w = fmaf(pi, v0v.w, av[i][0].w);
                av[i][1].x = fmaf(pi, v1v.x, av[i][1].x);
                av[i][1].y = fmaf(pi, v1v.y, av[i][1].y);
                av[i][1].z = fmaf(pi, v1v.z, av[i][1].z);
                av[i][1].w = fmaf(pi, v1v.w, av[i][1].w);
                av[i][2].x = fmaf(pi, v2v.x, av[i][2].x);
                av[i][2].y = fmaf(pi, v2v.y, av[i][2].y);
                av[i][2].z = fmaf(pi, v2v.z, av[i][2].z);
                av[i][2].w = fmaf(pi, v2v.w, av[i][2].w);
                av[i][3].x = fmaf(pi, v3v.x, av[i][3].x);
                av[i][3].y = fmaf(pi, v3v.y, av[i][3].y);
                av[i][3].z = fmaf(pi, v3v.z, av[i][3].z);
                av[i][3].w = fmaf(pi, v3v.w, av[i][3].w);
            }
        }
    }

    #pragma unroll
    for (int i = 0; i < 4; i++) {
        float inv = 1.0f / lsum[i];
        size_t ob = (size_t)(b*TT + q0 + i) * DD + h*HD + d0;
        #pragma unroll
        for (int c = 0; c < 4; c++) {
            float f[4] = { av[i][c].x*inv, av[i][c].y*inv, av[i][c].z*inv, av[i][c].w*inv };
            #pragma unroll
            for (int e = 0; e < 2; e++) {
                __nv_bfloat16 h0 = __float2bfloat16(f[e*2]);
                __nv_bfloat16 h1 = __float2bfloat16(f[e*2+1]);
                *(__nv_bfloat162*)&oh[ob + c*4 + e*2] = __nv_bfloat162(h0, h1);
                __nv_bfloat16 l0 = __float2bfloat16(f[e*2]   - __bfloat162float(h0));
                __nv_bfloat16 l1 = __float2bfloat16(f[e*2+1] - __bfloat162float(h1));
                *(__nv_bfloat162*)&ol[ob + c*4 + e*2] = __nv_bfloat162(l0, l1);
            }
        }
    }
}

// ---------------- Driver ---------------------------
extern "C" void kernel_launch(void* const* d_in, const int* in_sizes, int n_in,
                              void* d_out, int out_size) {
    (void)in_sizes; (void)n_in; (void)out_size;
    const int*   x       = (const int*)  d_in[0];
    const float* tok_emb = (const float*)d_in[1];
    const float* pos_emb = (const float*)d_in[2];
    const float* qkv_w   = (const float*)d_in[3];
    const float* fc_w    = (const float*)d_in[4];
    const float* fc_b    = (const float*)d_in[5];
    const float* ln1_s   = (const float*)d_in[6];
    const float* ln1_b   = (const float*)d_in[7];
    const float* ln2_s   = (const float*)d_in[8];
    const float* ln2_b   = (const float*)d_in[9];
    const float* ff1_w   = (const float*)d_in[10];
    const float* ff1_b   = (const float*)d_in[11];
    const float* ff2_w   = (const float*)d_in[12];
    const float* ff2_b   = (const float*)d_in[13];
    const float* lnf_s   = (const float*)d_in[14];
    const float* lnf_b   = (const float*)d_in[15];
    const float* out_w   = (const float*)d_in[16];
    const float* out_b   = (const float*)d_in[17];
    float* logits = (float*)d_out;

    cudaFuncSetAttribute(mm_kernel<2>, cudaFuncAttributeMaxDynamicSharedMemorySize, GEMM_SMEM);
    cudaFuncSetAttribute(mm_big<0>, cudaFuncAttributeMaxDynamicSharedMemorySize, GEMM2_SMEM);
    cudaFuncSetAttribute(mm_big<1>, cudaFuncAttributeMaxDynamicSharedMemorySize, GEMM2_SMEM);
    cudaFuncSetAttribute(mm_big<3>, cudaFuncAttributeMaxDynamicSharedMemorySize, GEMM2_SMEM);

    float *h, *qkvb;
    __nv_bfloat16 *xh, *xl, *ah, *al, *fh, *fl;
    __nv_bfloat16 *qh, *ql, *fch, *fcl, *f1h, *f1l, *f2h, *f2l, *oh, *ol;
    cudaGetSymbolAddress((void**)&h,    g_h);
    cudaGetSymbolAddress((void**)&qkvb, g_qkv);
    cudaGetSymbolAddress((void**)&xh, g_xh);  cudaGetSymbolAddress((void**)&xl, g_xl);
    cudaGetSymbolAddress((void**)&ah, g_ah);  cudaGetSymbolAddress((void**)&al, g_al);
    cudaGetSymbolAddress((void**)&fh, g_fh);  cudaGetSymbolAddress((void**)&fl, g_fl);
    cudaGetSymbolAddress((void**)&qh, w_qkvh); cudaGetSymbolAddress((void**)&ql, w_qkvl);
    cudaGetSymbolAddress((void**)&fch, w_fch); cudaGetSymbolAddress((void**)&fcl, w_fcl);
    cudaGetSymbolAddress((void**)&f1h, w_f1h); cudaGetSymbolAddress((void**)&f1l, w_f1l);
    cudaGetSymbolAddress((void**)&f2h, w_f2h); cudaGetSymbolAddress((void**)&f2l, w_f2l);
    cudaGetSymbolAddress((void**)&oh, w_oh);   cudaGetSymbolAddress((void**)&ol, w_ol);

    cvt_kernel<<<2048, 256>>>(qkv_w, qh, ql, LL*DQKV*DD/4);
    cvt_kernel<<<1024, 256>>>(fc_w,  fch, fcl, LL*DD*DD/4);
    cvt_kernel<<<2048, 256>>>(ff1_w, f1h, f1l, LL*DFF*DD/4);
    cvt_kernel<<<2048, 256>>>(ff2_w, f2h, f2l, LL*DD*DFF/4);
    cvt_kernel<<<4096, 256>>>(out_w, oh, ol, VV*DD/4);

    embed_kernel<<<NTOK, 256>>>(x, tok_emb, pos_emb);

    for (int l = 0; l < LL; l++) {
        const __nv_bfloat16* wqh = qh + (size_t)l * DQKV * DD;
        const __nv_bfloat16* wql = ql + (size_t)l * DQKV * DD;
        const __nv_bfloat16* wph = fch + (size_t)l * DD * DD;
        const __nv_bfloat16* wpl = fcl + (size_t)l * DD * DD;
        const __nv_bfloat16* w1h = f1h + (size_t)l * DFF * DD;
        const __nv_bfloat16* w1l = f1l + (size_t)l * DFF * DD;
        const __nv_bfloat16* w2h = f2h + (size_t)l * DD * DFF;
        const __nv_bfloat16* w2l = f2l + (size_t)l * DD * DFF;

        ln_kernel<<<NTOK, 256>>>(h, ln1_s + (size_t)l*DD, ln1_b + (size_t)l*DD, xh, xl);
        mm_big<0><<<dim3(NTOK/256, DQKV/128), 256, GEMM2_SMEM>>>(
            xh, xl, wqh, wql, nullptr, qkvb, nullptr, nullptr, DQKV, DD);
        attn_kernel<<<dim3(TT/256, BB*HH), 256>>>(qkvb, ah, al);
        mm_kernel<2><<<dim3(NTOK/128, DD/128), 256, GEMM_SMEM>>>(
            ah, al, wph, wpl, fc_b + (size_t)l*DD, h, nullptr, nullptr, DD, DD);
        ln_kernel<<<NTOK, 256>>>(h, ln2_s + (size_t)l*DD, ln2_b + (size_t)l*DD, xh, xl);
        mm_big<3><<<dim3(NTOK/256, DFF/128), 256, GEMM2_SMEM>>>(
            xh, xl, w1h, w1l, ff1_b + (size_t)l*DFF, nullptr, fh, fl, DFF, DD);
        mm_kernel<2><<<dim3(NTOK/128, DD/128), 256, GEMM_SMEM>>>(
            fh, fl, w2h, w2l, ff2_b + (size_t)l*DD, h, nullptr, nullptr, DD, DFF);
    }

    ln_kernel<<<NTOK, 256>>>(h, lnf_s, lnf_b, xh, xl);
    mm_big<1><<<dim3(NTOK/256, VV/128), 256, GEMM2_SMEM>>>(
        xh, xl, oh, ol, out_b, logits, nullptr, nullptr, VV, DD);
}

// round 7
// speedup vs baseline: 1.0226x; 1.0226x over previous
#include <cuda_runtime.h>
#include <cuda_bf16.h>
#include <math.h>
#include <stdint.h>

// ---------------- Problem constants ----------------
#define BB    4
#define TT    1024
#define NTOK  (BB*TT)
#define DD    768
#define HH    12
#define HD    64
#define LL    6
#define VV    32000
#define DFF   3072
#define DQKV  2304
#define EPS   1e-5f

// ---------------- Static device buffers ------------
__device__ float g_h   [NTOK * DD];     // residual stream (fp32)
__device__ float g_qkv [NTOK * DQKV];   // qkv projections (fp32)
__device__ __nv_bfloat16 g_xh[NTOK*DD],  g_xl[NTOK*DD];    // LN out hi/lo
__device__ __nv_bfloat16 g_ah[NTOK*DD],  g_al[NTOK*DD];    // attn out hi/lo
__device__ __nv_bfloat16 g_fh[NTOK*DFF], g_fl[NTOK*DFF];   // relu out hi/lo
// bf16 hi/lo weight copies
__device__ __nv_bfloat16 w_qkvh[LL*DQKV*DD], w_qkvl[LL*DQKV*DD];
__device__ __nv_bfloat16 w_fch [LL*DD*DD],   w_fcl [LL*DD*DD];
__device__ __nv_bfloat16 w_f1h [LL*DFF*DD],  w_f1l [LL*DFF*DD];
__device__ __nv_bfloat16 w_f2h [LL*DD*DFF],  w_f2l [LL*DD*DFF];
__device__ __nv_bfloat16 w_oh  [VV*DD],      w_ol  [VV*DD];

// ---------------- PTX helpers (arch-generic only) ---
__device__ __forceinline__ uint32_t smem_to_u32(const void* p) {
    uint32_t a;
    asm("{ .reg .u64 t; cvta.to.shared.u64 t, %1; cvt.u32.u64 %0, t; }"
        : "=r"(a) : "l"(p));
    return a;
}
#define CP_ASYNC16(dst, src) \
    asm volatile("cp.async.cg.shared.global [%0], [%1], 16;" :: "r"(dst), "l"(src))
#define CP_COMMIT asm volatile("cp.async.commit_group;" ::: "memory")
#define CP_WAIT1  asm volatile("cp.async.wait_group 1;" ::: "memory")
#define CP_WAIT0  asm volatile("cp.async.wait_group 0;" ::: "memory")

__device__ __forceinline__ void ldsm4(uint32_t* r, uint32_t addr) {
    asm volatile("ldmatrix.sync.aligned.m8n8.x4.shared.b16 {%0,%1,%2,%3}, [%4];"
        : "=r"(r[0]), "=r"(r[1]), "=r"(r[2]), "=r"(r[3]) : "r"(addr));
}
__device__ __forceinline__ void ldsm2(uint32_t* r, uint32_t addr) {
    asm volatile("ldmatrix.sync.aligned.m8n8.x2.shared.b16 {%0,%1}, [%2];"
        : "=r"(r[0]), "=r"(r[1]) : "r"(addr));
}
__device__ __forceinline__ void mma_bf16(float* d, const uint32_t* a, const uint32_t* b) {
    asm volatile("mma.sync.aligned.m16n8k16.row.col.f32.bf16.bf16.f32 "
        "{%0,%1,%2,%3}, {%4,%5,%6,%7}, {%8,%9}, {%0,%1,%2,%3};"
        : "+f"(d[0]), "+f"(d[1]), "+f"(d[2]), "+f"(d[3])
        : "r"(a[0]), "r"(a[1]), "r"(a[2]), "r"(a[3]), "r"(b[0]), "r"(b[1]));
}

// fast exp on FMA pipe (no MUFU), deg-7 Horner, rel err ~1e-6 for x <= 0.
__device__ __forceinline__ float fexp(float x) {
    float t = x * 1.4426950408889634f;
    t = fmaxf(t, -126.0f);
    float n = floorf(t);
    float f = (t - n) * 0.6931471805599453f;
    float p = 1.98412698e-4f;
    p = fmaf(p, f, 1.38888889e-3f);
    p = fmaf(p, f, 8.33333333e-3f);
    p = fmaf(p, f, 4.16666667e-2f);
    p = fmaf(p, f, 1.66666667e-1f);
    p = fmaf(p, f, 5.0e-1f);
    p = fmaf(p, f, 1.0f);
    p = fmaf(p, f, 1.0f);
    float sc = __int_as_float(((int)n + 127) << 23);
    return p * sc;
}

// ---------------- Embedding ------------------------
__global__ void embed_kernel(const int* __restrict__ x,
                             const float* __restrict__ tok_emb,
                             const float* __restrict__ pos_emb) {
    int row = blockIdx.x;
    int t   = row % TT;
    int id  = x[row];
    const float* te = tok_emb + (size_t)id * DD;
    const float* pe = pos_emb + (size_t)t  * DD;
    float* out = g_h + (size_t)row * DD;
    for (int i = threadIdx.x; i < DD; i += blockDim.x)
        out[i] = te[i] + pe[i];
}

// ---------------- fp32 -> bf16 hi/lo split ---------
__global__ void cvt_kernel(const float* __restrict__ s,
                           __nv_bfloat16* __restrict__ hi,
                           __nv_bfloat16* __restrict__ lo, int n4) {
    int i = blockIdx.x * blockDim.x + threadIdx.x;
    int stride = gridDim.x * blockDim.x;
    for (; i < n4; i += stride) {
        float4 v = ((const float4*)s)[i];
        __nv_bfloat16 h0 = __float2bfloat16(v.x);
        __nv_bfloat16 h1 = __float2bfloat16(v.y);
        __nv_bfloat16 h2 = __float2bfloat16(v.z);
        __nv_bfloat16 h3 = __float2bfloat16(v.w);
        __nv_bfloat16 l0 = __float2bfloat16(v.x - __bfloat162float(h0));
        __nv_bfloat16 l1 = __float2bfloat16(v.y - __bfloat162float(h1));
        __nv_bfloat16 l2 = __float2bfloat16(v.z - __bfloat162float(h2));
        __nv_bfloat16 l3 = __float2bfloat16(v.w - __bfloat162float(h3));
        __nv_bfloat162* ph = (__nv_bfloat162*)hi + i*2;
        __nv_bfloat162* pl = (__nv_bfloat162*)lo + i*2;
        ph[0] = __nv_bfloat162(h0, h1); ph[1] = __nv_bfloat162(h2, h3);
        pl[0] = __nv_bfloat162(l0, l1); pl[1] = __nv_bfloat162(l2, l3);
    }
}

// ---------------- LayerNorm -> bf16 hi/lo ----------
__device__ __forceinline__ float block_reduce_sum(float v, float* red) {
    int lane = threadIdx.x & 31, wid = threadIdx.x >> 5;
    #pragma unroll
    for (int o = 16; o > 0; o >>= 1) v += __shfl_xor_sync(0xffffffffu, v, o);
    if (lane == 0) red[wid] = v;
    __syncthreads();
    if (wid == 0) {
        float w = (lane < (blockDim.x >> 5)) ? red[lane] : 0.f;
        #pragma unroll
        for (int o = 4; o > 0; o >>= 1) w += __shfl_xor_sync(0xffffffffu, w, o);
        if (lane == 0) red[0] = w;
    }
    __syncthreads();
    float r = red[0];
    __syncthreads();
    return r;
}

__global__ void ln_kernel(const float* __restrict__ xin,
                          const float* __restrict__ sc,
                          const float* __restrict__ bi,
                          __nv_bfloat16* __restrict__ yh,
                          __nv_bfloat16* __restrict__ yl) {
    __shared__ float red[32];
    int row = blockIdx.x;
    const float* xr = xin + (size_t)row * DD;
    float xv[3];
    float s = 0.f;
    #pragma unroll
    for (int i = 0; i < 3; i++) { xv[i] = xr[threadIdx.x + i*256]; s += xv[i]; }
    float mean = block_reduce_sum(s, red) * (1.0f / DD);
    float vs = 0.f;
    #pragma unroll
    for (int i = 0; i < 3; i++) { float d = xv[i] - mean; vs += d * d; }
    float var = block_reduce_sum(vs, red) * (1.0f / DD);
    float rstd = rsqrtf(var + EPS);
    #pragma unroll
    for (int i = 0; i < 3; i++) {
        int c = threadIdx.x + i*256;
        float v = (xv[i] - mean) * rstd * sc[c] + bi[c];
        __nv_bfloat16 h = __float2bfloat16(v);
        yh[(size_t)row*DD + c] = h;
        yl[(size_t)row*DD + c] = __float2bfloat16(v - __bfloat162float(h));
    }
}

// =============== 128x128 HMMA GEMM (validated @ 9.38ms config) =============
#define KC         64
#define TILE_B     16384
#define STG_B      (4*TILE_B)
#define GEMM_SMEM  (2*STG_B)

template<int OP>
__global__ __launch_bounds__(256, 1)
void mm_kernel(const __nv_bfloat16* __restrict__ Ah, const __nv_bfloat16* __restrict__ Al,
               const __nv_bfloat16* __restrict__ Wh, const __nv_bfloat16* __restrict__ Wl,
               const float* __restrict__ bias, float* __restrict__ C,
               __nv_bfloat16* __restrict__ Oh, __nv_bfloat16* __restrict__ Ol,
               int N, int K) {
    extern __shared__ char smem[];
    const uint32_t sb = smem_to_u32(smem);
    int tid = threadIdx.x, lane = tid & 31, warp = tid >> 5;
    int wm = warp >> 2;
    int wn = warp & 3;
    int bm = blockIdx.x * 128, bn = blockIdx.y * 128;

    float acc[4][4][4];
    #pragma unroll
    for (int i = 0; i < 4; i++)
        #pragma unroll
        for (int j = 0; j < 4; j++)
            #pragma unroll
            for (int k = 0; k < 4; k++) acc[i][j][k] = 0.f;

    int crow = tid >> 1;
    int cch0 = (tid & 1) * 4;
    const __nv_bfloat16* gA_h = Ah + (size_t)(bm + crow) * K + cch0 * 8;
    const __nv_bfloat16* gA_l = Al + (size_t)(bm + crow) * K + cch0 * 8;
    const __nv_bfloat16* gW_h = Wh + (size_t)(bn + crow) * K + cch0 * 8;
    const __nv_bfloat16* gW_l = Wl + (size_t)(bn + crow) * K + cch0 * 8;
    uint32_t srow = (uint32_t)crow * 128;
    int rsw = crow & 7;

    int mat = lane >> 3, r8 = lane & 7;
    int a_kh = mat >> 1;
    uint32_t arowb[4]; int aswz[4];
    #pragma unroll
    for (int ti = 0; ti < 4; ti++) {
        int row = wm*64 + ti*16 + (mat & 1)*8 + r8;
        arowb[ti] = (uint32_t)row * 128;
        aswz[ti]  = row & 7;
    }
    int bl15 = lane & 15;
    int b_kh = bl15 >> 3;
    uint32_t browb[4]; int bswz[4];
    #pragma unroll
    for (int ni = 0; ni < 4; ni++) {
        int row = wn*32 + ni*8 + (bl15 & 7);
        browb[ni] = (uint32_t)row * 128;
        bswz[ni]  = row & 7;
    }

    const int nch = K / KC;
    {
        uint32_t st = sb;
        #pragma unroll
        for (int i = 0; i < 4; i++) {
            int c = cch0 + i;
            uint32_t soff = srow + (uint32_t)((c ^ rsw) << 4);
            CP_ASYNC16(st + soff,            gA_h + i*8);
            CP_ASYNC16(st + TILE_B + soff,   gA_l + i*8);
            CP_ASYNC16(st + 2*TILE_B + soff, gW_h + i*8);
            CP_ASYNC16(st + 3*TILE_B + soff, gW_l + i*8);
        }
        CP_COMMIT;
    }

    for (int ch = 0; ch < nch; ch++) {
        if (ch + 1 < nch) {
            uint32_t st = sb + ((ch + 1) & 1) * STG_B;
            int k0 = (ch + 1) * KC;
            #pragma unroll
            for (int i = 0; i < 4; i++) {
                int c = cch0 + i;
                uint32_t soff = srow + (uint32_t)((c ^ rsw) << 4);
                CP_ASYNC16(st + soff,            gA_h + k0 + i*8);
                CP_ASYNC16(st + TILE_B + soff,   gA_l + k0 + i*8);
                CP_ASYNC16(st + 2*TILE_B + soff, gW_h + k0 + i*8);
                CP_ASYNC16(st + 3*TILE_B + soff, gW_l + k0 + i*8);
            }
            CP_COMMIT;
            CP_WAIT1;
        } else {
            CP_WAIT0;
        }
        __syncthreads();

        uint32_t stA = sb + (ch & 1) * STG_B;
        uint32_t stW = stA + 2*TILE_B;
        #pragma unroll
        for (int ks = 0; ks < 4; ks++) {
            uint32_t ahf[4][4], alf[4][4];
            #pragma unroll
            for (int ti = 0; ti < 4; ti++) {
                uint32_t off = arowb[ti] + (uint32_t)((((ks << 1) | a_kh) ^ aswz[ti]) << 4);
                ldsm4(ahf[ti], stA + off);
                ldsm4(alf[ti], stA + TILE_B + off);
            }
            uint32_t bhf[4][2], blf[4][2];
            #pragma unroll
            for (int ni = 0; ni < 4; ni++) {
                uint32_t off = browb[ni] + (uint32_t)((((ks << 1) | b_kh) ^ bswz[ni]) << 4);
                ldsm2(bhf[ni], stW + off);
                ldsm2(blf[ni], stW + TILE_B + off);
            }
            #pragma unroll
            for (int ti = 0; ti < 4; ti++)
                #pragma unroll
                for (int ni = 0; ni < 4; ni++) {
                    mma_bf16(acc[ti][ni], ahf[ti], bhf[ni]);
                    mma_bf16(acc[ti][ni], ahf[ti], blf[ni]);
                    mma_bf16(acc[ti][ni], alf[ti], bhf[ni]);
                }
        }
        __syncthreads();
    }

    int lr = lane >> 2, lc = (lane & 3) * 2;
    #pragma unroll
    for (int ti = 0; ti < 4; ti++) {
        #pragma unroll
        for (int ni = 0; ni < 4; ni++) {
            int grow = bm + wm*64 + ti*16 + lr;
            int gcol = bn + wn*32 + ni*8 + lc;
            #pragma unroll
            for (int half = 0; half < 2; half++) {
                int r = grow + half*8;
                size_t off = (size_t)r * N + gcol;
                float v0 = acc[ti][ni][half*2 + 0];
                float v1 = acc[ti][ni][half*2 + 1];
                if (OP == 0) {
                    *(float2*)&C[off] = make_float2(v0, v1);
                } else if (OP == 1) {
                    *(float2*)&C[off] = make_float2(v0 + bias[gcol], v1 + bias[gcol+1]);
                } else if (OP == 2) {
                    float2 hcur = *(float2*)&C[off];
                    *(float2*)&C[off] = make_float2(v0 + bias[gcol]   + hcur.x,
                                                    v1 + bias[gcol+1] + hcur.y);
                } else {
                    float f0 = fmaxf(v0 + bias[gcol],   0.f);
                    float f1 = fmaxf(v1 + bias[gcol+1], 0.f);
                    __nv_bfloat16 h0 = __float2bfloat16(f0);
                    __nv_bfloat16 h1 = __float2bfloat16(f1);
                    *(__nv_bfloat162*)&Oh[off] = __nv_bfloat162(h0, h1);
                    __nv_bfloat16 l0 = __float2bfloat16(f0 - __bfloat162float(h0));
                    __nv_bfloat16 l1 = __float2bfloat16(f1 - __bfloat162float(h1));
                    *(__nv_bfloat162*)&Ol[off] = __nv_bfloat162(l0, l1);
                }
            }
        }
    }
}

// =============== Causal attention: 4 q/thread, 16-dim lane slice ===========
// Warp-uniform inner trip count (qwmax); causality via per-query predicate,
// which is quad-uniform so all shfl participants agree.
__global__ __launch_bounds__(256)
void attn_kernel(const float* __restrict__ qkv,
                 __nv_bfloat16* __restrict__ oh, __nv_bfloat16* __restrict__ ol) {
    __shared__ float Ks[64][64];
    __shared__ float Vs[64][64];

    int bh = blockIdx.y;
    int b  = bh / HH, h = bh % HH;
    int tid = threadIdx.x;
    int warp = tid >> 5;
    int quad = tid >> 2, dg = tid & 3;
    int q0 = blockIdx.x * 256 + quad * 4;
    int d0 = dg * 16;
    int qwmax = blockIdx.x * 256 + warp * 32 + 31;

    float4 qr[4][4];
    #pragma unroll
    for (int i = 0; i < 4; i++) {
        const float4* qp = (const float4*)(qkv + (size_t)(b*TT + q0 + i) * DQKV + h*HD + d0);
        #pragma unroll
        for (int c = 0; c < 4; c++) {
            qr[i][c] = qp[c];
            qr[i][c].x *= 0.125f; qr[i][c].y *= 0.125f;
            qr[i][c].z *= 0.125f; qr[i][c].w *= 0.125f;
        }
    }
    float4 av[4][4];
    #pragma unroll
    for (int i = 0; i < 4; i++)
        #pragma unroll
        for (int c = 0; c < 4; c++) av[i][c] = make_float4(0.f,0.f,0.f,0.f);
    float m[4], lsum[4];
    #pragma unroll
    for (int i = 0; i < 4; i++) { m[i] = -1e30f; lsum[i] = 0.f; }

    int ntile = blockIdx.x * 4 + 4;
    int lrow = tid >> 2, lseg = (tid & 3) * 4;

    for (int kt = 0; kt < ntile; kt++) {
        const float* kb = qkv + (size_t)(b*TT + kt*64) * DQKV + DD + h*HD;
        const float* vb = kb + DD;
        __syncthreads();
        {
            const float4* ksrc = (const float4*)(kb + (size_t)lrow * DQKV);
            const float4* vsrc = (const float4*)(vb + (size_t)lrow * DQKV);
            float4* kdst = (float4*)&Ks[lrow][0];
            float4* vdst = (float4*)&Vs[lrow][0];
            #pragma unroll
            for (int c = 0; c < 4; c++) {
                kdst[lseg + c] = ksrc[lseg + c];
                vdst[lseg + c] = vsrc[lseg + c];
            }
        }
        __syncthreads();

        int jm = qwmax - kt*64 + 1;
        jm = (jm > 64) ? 64 : jm;
        if (jm <= 0) continue;
        for (int j = 0; j < jm; j++) {
            const float4* kr = (const float4*)&Ks[j][d0];
            float4 k0v = kr[0], k1v = kr[1], k2v = kr[2], k3v = kr[3];
            float sp[4];
            #pragma unroll
            for (int i = 0; i < 4; i++) {
                float s;
                s  = qr[i][0].x*k0v.x + qr[i][0].y*k0v.y + qr[i][0].z*k0v.z + qr[i][0].w*k0v.w;
                s += qr[i][1].x*k1v.x + qr[i][1].y*k1v.y + qr[i][1].z*k1v.z + qr[i][1].w*k1v.w;
                s += qr[i][2].x*k2v.x + qr[i][2].y*k2v.y + qr[i][2].z*k2v.z + qr[i][2].w*k2v.w;
                s += qr[i][3].x*k3v.x + qr[i][3].y*k3v.y + qr[i][3].z*k3v.z + qr[i][3].w*k3v.w;
                sp[i] = s;
            }
            #pragma unroll
            for (int i = 0; i < 4; i++) {
                sp[i] += __shfl_xor_sync(0xffffffffu, sp[i], 1);
                sp[i] += __shfl_xor_sync(0xffffffffu, sp[i], 2);
            }
            int rel = kt*64 + j;
            float p[4];
            #pragma unroll
            for (int i = 0; i < 4; i++) {
                bool ok = (rel <= q0 + i);
                float s = sp[i];
                if (ok && s > m[i]) {
                    float corr = fexp(m[i] - s);
                    #pragma unroll
                    for (int c = 0; c < 4; c++) {
                        av[i][c].x *= corr; av[i][c].y *= corr;
                        av[i][c].z *= corr; av[i][c].w *= corr;
                    }
                    lsum[i] = lsum[i] * corr + 1.f;
                    m[i] = s;
                    p[i] = 1.f;
                } else {
                    p[i] = ok ? fexp(s - m[i]) : 0.f;
                    lsum[i] += p[i];
                }
            }
            const float4* vr = (const float4*)&Vs[j][d0];
            float4 v0v = vr[0], v1v = vr[1], v2v = vr[2], v3v = vr[3];
            #pragma unroll
            for (int i = 0; i < 4; i++) {
                float pi = p[i];
                av[i][0].x = fmaf(pi, v0v.x, av[i][0].x);
                av[i][0].y = fmaf(pi, v0v.y, av[i][0].y);
                av[i][0].z = fmaf(pi, v0v.z, av[i][0].z);
                av[i][0].w = fmaf(pi, v0v.w, av[i][0].w);
                av[i][1].x = fmaf(pi, v1v.x, av[i][1].x);
                av[i][1].y = fmaf(pi, v1v.y, av[i][1].y);
                av[i][1].z = fmaf(pi, v1v.z, av[i][1].z);
                av[i][1].w = fmaf(pi, v1v.w, av[i][1].w);
                av[i][2].x = fmaf(pi, v2v.x, av[i][2].x);
                av[i][2].y = fmaf(pi, v2v.y, av[i][2].y);
                av[i][2].z = fmaf(pi, v2v.z, av[i][2].z);
                av[i][2].w = fmaf(pi, v2v.w, av[i][2].w);
                av[i][3].x = fmaf(pi, v3v.x, av[i][3].x);
                av[i][3].y = fmaf(pi, v3v.y, av[i][3].y);
                av[i][3].z = fmaf(pi, v3v.z, av[i][3].z);
                av[i][3].w = fmaf(pi, v3v.w, av[i][3].w);
            }
        }
    }

    #pragma unroll
    for (int i = 0; i < 4; i++) {
        float inv = 1.0f / lsum[i];
        size_t ob = (size_t)(b*TT + q0 + i) * DD + h*HD + d0;
        #pragma unroll
        for (int c = 0; c < 4; c++) {
            float f[4] = { av[i][c].x*inv, av[i][c].y*inv, av[i][c].z*inv, av[i][c].w*inv };
            #pragma unroll
            for (int e = 0; e < 2; e++) {
                __nv_bfloat16 h0 = __float2bfloat16(f[e*2]);
                __nv_bfloat16 h1 = __float2bfloat16(f[e*2+1]);
                *(__nv_bfloat162*)&oh[ob + c*4 + e*2] = __nv_bfloat162(h0, h1);
                __nv_bfloat16 l0 = __float2bfloat16(f[e*2]   - __bfloat162float(h0));
                __nv_bfloat16 l1 = __float2bfloat16(f[e*2+1] - __bfloat162float(h1));
                *(__nv_bfloat162*)&ol[ob + c*4 + e*2] = __nv_bfloat162(l0, l1);
            }
        }
    }
}

// ---------------- Driver ---------------------------
extern "C" void kernel_launch(void* const* d_in, const int* in_sizes, int n_in,
                              void* d_out, int out_size) {
    (void)in_sizes; (void)n_in; (void)out_size;
    const int*   x       = (const int*)  d_in[0];
    const float* tok_emb = (const float*)d_in[1];
    const float* pos_emb = (const float*)d_in[2];
    const float* qkv_w   = (const float*)d_in[3];
    const float* fc_w    = (const float*)d_in[4];
    const float* fc_b    = (const float*)d_in[5];
    const float* ln1_s   = (const float*)d_in[6];
    const float* ln1_b   = (const float*)d_in[7];
    const float* ln2_s   = (const float*)d_in[8];
    const float* ln2_b   = (const float*)d_in[9];
    const float* ff1_w   = (const float*)d_in[10];
    const float* ff1_b   = (const float*)d_in[11];
    const float* ff2_w   = (const float*)d_in[12];
    const float* ff2_b   = (const float*)d_in[13];
    const float* lnf_s   = (const float*)d_in[14];
    const float* lnf_b   = (const float*)d_in[15];
    const float* out_w   = (const float*)d_in[16];
    const float* out_b   = (const float*)d_in[17];
    float* logits = (float*)d_out;

    cudaFuncSetAttribute(mm_kernel<0>, cudaFuncAttributeMaxDynamicSharedMemorySize, GEMM_SMEM);
    cudaFuncSetAttribute(mm_kernel<1>, cudaFuncAttributeMaxDynamicSharedMemorySize, GEMM_SMEM);
    cudaFuncSetAttribute(mm_kernel<2>, cudaFuncAttributeMaxDynamicSharedMemorySize, GEMM_SMEM);
    cudaFuncSetAttribute(mm_kernel<3>, cudaFuncAttributeMaxDynamicSharedMemorySize, GEMM_SMEM);

    float *h, *qkvb;
    __nv_bfloat16 *xh, *xl, *ah, *al, *fh, *fl;
    __nv_bfloat16 *qh, *ql, *fch, *fcl, *f1h, *f1l, *f2h, *f2l, *oh, *ol;
    cudaGetSymbolAddress((void**)&h,    g_h);
    cudaGetSymbolAddress((void**)&qkvb, g_qkv);
    cudaGetSymbolAddress((void**)&xh, g_xh);  cudaGetSymbolAddress((void**)&xl, g_xl);
    cudaGetSymbolAddress((void**)&ah, g_ah);  cudaGetSymbolAddress((void**)&al, g_al);
    cudaGetSymbolAddress((void**)&fh, g_fh);  cudaGetSymbolAddress((void**)&fl, g_fl);
    cudaGetSymbolAddress((void**)&qh, w_qkvh); cudaGetSymbolAddress((void**)&ql, w_qkvl);
    cudaGetSymbolAddress((void**)&fch, w_fch); cudaGetSymbolAddress((void**)&fcl, w_fcl);
    cudaGetSymbolAddress((void**)&f1h, w_f1h); cudaGetSymbolAddress((void**)&f1l, w_f1l);
    cudaGetSymbolAddress((void**)&f2h, w_f2h); cudaGetSymbolAddress((void**)&f2l, w_f2l);
    cudaGetSymbolAddress((void**)&oh, w_oh);   cudaGetSymbolAddress((void**)&ol, w_ol);

    cvt_kernel<<<2048, 256>>>(qkv_w, qh, ql, LL*DQKV*DD/4);
    cvt_kernel<<<1024, 256>>>(fc_w,  fch, fcl, LL*DD*DD/4);
    cvt_kernel<<<2048, 256>>>(ff1_w, f1h, f1l, LL*DFF*DD/4);
    cvt_kernel<<<2048, 256>>>(ff2_w, f2h, f2l, LL*DD*DFF/4);
    cvt_kernel<<<4096, 256>>>(out_w, oh, ol, VV*DD/4);

    embed_kernel<<<NTOK, 256>>>(x, tok_emb, pos_emb);

    for (int l = 0; l < LL; l++) {
        const __nv_bfloat16* wqh = qh + (size_t)l * DQKV * DD;
        const __nv_bfloat16* wql = ql + (size_t)l * DQKV * DD;
        const __nv_bfloat16* wph = fch + (size_t)l * DD * DD;
        const __nv_bfloat16* wpl = fcl + (size_t)l * DD * DD;
        const __nv_bfloat16* w1h = f1h + (size_t)l * DFF * DD;
        const __nv_bfloat16* w1l = f1l + (size_t)l * DFF * DD;
        const __nv_bfloat16* w2h = f2h + (size_t)l * DD * DFF;
        const __nv_bfloat16* w2l = f2l + (size_t)l * DD * DFF;

        ln_kernel<<<NTOK, 256>>>(h, ln1_s + (size_t)l*DD, ln1_b + (size_t)l*DD, xh, xl);
        mm_kernel<0><<<dim3(NTOK/128, DQKV/128), 256, GEMM_SMEM>>>(
            xh, xl, wqh, wql, nullptr, qkvb, nullptr, nullptr, DQKV, DD);
        attn_kernel<<<dim3(TT/256, BB*HH), 256>>>(qkvb, ah, al);
        mm_kernel<2><<<dim3(NTOK/128, DD/128), 256, GEMM_SMEM>>>(
            ah, al, wph, wpl, fc_b + (size_t)l*DD, h, nullptr, nullptr, DD, DD);
        ln_kernel<<<NTOK, 256>>>(h, ln2_s + (size_t)l*DD, ln2_b + (size_t)l*DD, xh, xl);
        mm_kernel<3><<<dim3(NTOK/128, DFF/128), 256, GEMM_SMEM>>>(
            xh, xl, w1h, w1l, ff1_b + (size_t)l*DFF, nullptr, fh, fl, DFF, DD);
        mm_kernel<2><<<dim3(NTOK/128, DD/128), 256, GEMM_SMEM>>>(
            fh, fl, w2h, w2l, ff2_b + (size_t)l*DD, h, nullptr, nullptr, DD, DFF);
    }

    ln_kernel<<<NTOK, 256>>>(h, lnf_s, lnf_b, xh, xl);
    mm_kernel<1><<<dim3(NTOK/128, VV/128), 256, GEMM_SMEM>>>(
        xh, xl, oh, ol, out_b, logits, nullptr, nullptr, VV, DD);
}

// round 8
// speedup vs baseline: 1.4469x; 1.4149x over previous
#include <cuda_runtime.h>
#include <cuda_bf16.h>
#include <math.h>
#include <stdint.h>

// ---------------- Problem constants ----------------
#define BB    4
#define TT    1024
#define NTOK  (BB*TT)
#define DD    768
#define HH    12
#define HD    64
#define LL    6
#define VV    32000
#define DFF   3072
#define DQKV  2304
#define EPS   1e-5f

// ---------------- Static device buffers ------------
__device__ float g_h   [NTOK * DD];     // residual stream (fp32)
__device__ float g_qkv [NTOK * DQKV];   // qkv projections (fp32)
__device__ __nv_bfloat16 g_xh[NTOK*DD],  g_xl[NTOK*DD];    // LN out hi/lo
__device__ __nv_bfloat16 g_ah[NTOK*DD],  g_al[NTOK*DD];    // attn out hi/lo
__device__ __nv_bfloat16 g_fh[NTOK*DFF], g_fl[NTOK*DFF];   // relu out hi/lo
// bf16 hi/lo weight copies
__device__ __nv_bfloat16 w_qkvh[LL*DQKV*DD], w_qkvl[LL*DQKV*DD];
__device__ __nv_bfloat16 w_fch [LL*DD*DD],   w_fcl [LL*DD*DD];
__device__ __nv_bfloat16 w_f1h [LL*DFF*DD],  w_f1l [LL*DFF*DD];
__device__ __nv_bfloat16 w_f2h [LL*DD*DFF],  w_f2l [LL*DD*DFF];
__device__ __nv_bfloat16 w_oh  [VV*DD],      w_ol  [VV*DD];

// ---------------- PTX helpers (arch-generic only) ---
__device__ __forceinline__ uint32_t smem_to_u32(const void* p) {
    uint32_t a;
    asm("{ .reg .u64 t; cvta.to.shared.u64 t, %1; cvt.u32.u64 %0, t; }"
        : "=r"(a) : "l"(p));
    return a;
}
#define CP_ASYNC16(dst, src) \
    asm volatile("cp.async.cg.shared.global [%0], [%1], 16;" :: "r"(dst), "l"(src))
#define CP_COMMIT asm volatile("cp.async.commit_group;" ::: "memory")
#define CP_WAIT1  asm volatile("cp.async.wait_group 1;" ::: "memory")
#define CP_WAIT0  asm volatile("cp.async.wait_group 0;" ::: "memory")

__device__ __forceinline__ void ldsm4(uint32_t* r, uint32_t addr) {
    asm volatile("ldmatrix.sync.aligned.m8n8.x4.shared.b16 {%0,%1,%2,%3}, [%4];"
        : "=r"(r[0]), "=r"(r[1]), "=r"(r[2]), "=r"(r[3]) : "r"(addr));
}
__device__ __forceinline__ void ldsm2(uint32_t* r, uint32_t addr) {
    asm volatile("ldmatrix.sync.aligned.m8n8.x2.shared.b16 {%0,%1}, [%2];"
        : "=r"(r[0]), "=r"(r[1]) : "r"(addr));
}
__device__ __forceinline__ void mma_bf16(float* d, const uint32_t* a, const uint32_t* b) {
    asm volatile("mma.sync.aligned.m16n8k16.row.col.f32.bf16.bf16.f32 "
        "{%0,%1,%2,%3}, {%4,%5,%6,%7}, {%8,%9}, {%0,%1,%2,%3};"
        : "+f"(d[0]), "+f"(d[1]), "+f"(d[2]), "+f"(d[3])
        : "r"(a[0]), "r"(a[1]), "r"(a[2]), "r"(a[3]), "r"(b[0]), "r"(b[1]));
}

// ---------------- Embedding ------------------------
__global__ void embed_kernel(const int* __restrict__ x,
                             const float* __restrict__ tok_emb,
                             const float* __restrict__ pos_emb) {
    int row = blockIdx.x;
    int t   = row % TT;
    int id  = x[row];
    const float* te = tok_emb + (size_t)id * DD;
    const float* pe = pos_emb + (size_t)t  * DD;
    float* out = g_h + (size_t)row * DD;
    for (int i = threadIdx.x; i < DD; i += blockDim.x)
        out[i] = te[i] + pe[i];
}

// ---------------- fp32 -> bf16 hi/lo split ---------
__global__ void cvt_kernel(const float* __restrict__ s,
                           __nv_bfloat16* __restrict__ hi,
                           __nv_bfloat16* __restrict__ lo, int n4) {
    int i = blockIdx.x * blockDim.x + threadIdx.x;
    int stride = gridDim.x * blockDim.x;
    for (; i < n4; i += stride) {
        float4 v = ((const float4*)s)[i];
        __nv_bfloat16 h0 = __float2bfloat16(v.x);
        __nv_bfloat16 h1 = __float2bfloat16(v.y);
        __nv_bfloat16 h2 = __float2bfloat16(v.z);
        __nv_bfloat16 h3 = __float2bfloat16(v.w);
        __nv_bfloat16 l0 = __float2bfloat16(v.x - __bfloat162float(h0));
        __nv_bfloat16 l1 = __float2bfloat16(v.y - __bfloat162float(h1));
        __nv_bfloat16 l2 = __float2bfloat16(v.z - __bfloat162float(h2));
        __nv_bfloat16 l3 = __float2bfloat16(v.w - __bfloat162float(h3));
        __nv_bfloat162* ph = (__nv_bfloat162*)hi + i*2;
        __nv_bfloat162* pl = (__nv_bfloat162*)lo + i*2;
        ph[0] = __nv_bfloat162(h0, h1); ph[1] = __nv_bfloat162(h2, h3);
        pl[0] = __nv_bfloat162(l0, l1); pl[1] = __nv_bfloat162(l2, l3);
    }
}

// ---------------- LayerNorm -> bf16 hi/lo ----------
__device__ __forceinline__ float block_reduce_sum(float v, float* red) {
    int lane = threadIdx.x & 31, wid = threadIdx.x >> 5;
    #pragma unroll
    for (int o = 16; o > 0; o >>= 1) v += __shfl_xor_sync(0xffffffffu, v, o);
    if (lane == 0) red[wid] = v;
    __syncthreads();
    if (wid == 0) {
        float w = (lane < (blockDim.x >> 5)) ? red[lane] : 0.f;
        #pragma unroll
        for (int o = 4; o > 0; o >>= 1) w += __shfl_xor_sync(0xffffffffu, w, o);
        if (lane == 0) red[0] = w;
    }
    __syncthreads();
    float r = red[0];
    __syncthreads();
    return r;
}

__global__ void ln_kernel(const float* __restrict__ xin,
                          const float* __restrict__ sc,
                          const float* __restrict__ bi,
                          __nv_bfloat16* __restrict__ yh,
                          __nv_bfloat16* __restrict__ yl) {
    __shared__ float red[32];
    int row = blockIdx.x;
    const float* xr = xin + (size_t)row * DD;
    float xv[3];
    float s = 0.f;
    #pragma unroll
    for (int i = 0; i < 3; i++) { xv[i] = xr[threadIdx.x + i*256]; s += xv[i]; }
    float mean = block_reduce_sum(s, red) * (1.0f / DD);
    float vs = 0.f;
    #pragma unroll
    for (int i = 0; i < 3; i++) { float d = xv[i] - mean; vs += d * d; }
    float var = block_reduce_sum(vs, red) * (1.0f / DD);
    float rstd = rsqrtf(var + EPS);
    #pragma unroll
    for (int i = 0; i < 3; i++) {
        int c = threadIdx.x + i*256;
        float v = (xv[i] - mean) * rstd * sc[c] + bi[c];
        __nv_bfloat16 h = __float2bfloat16(v);
        yh[(size_t)row*DD + c] = h;
        yl[(size_t)row*DD + c] = __float2bfloat16(v - __bfloat162float(h));
    }
}

// =============== 128x64 HMMA GEMM, 2 CTAs/SM ===============================
// Stage: Ah 16KB | Al 16KB | Wh 8KB | Wl 8KB = 48KB; 2 stages = 96KB.
// 8 warps as 4(M) x 2(N); warp tile 32x32.
#define KC         64
#define ATILE_B    16384
#define WTILE_B    8192
#define S_AH       0
#define S_AL       16384
#define S_WH       32768
#define S_WL       40960
#define STG_B      49152
#define GEMM_SMEM  (2*STG_B)

template<int OP>
__global__ __launch_bounds__(256, 2)
void mm_kernel(const __nv_bfloat16* __restrict__ Ah, const __nv_bfloat16* __restrict__ Al,
               const __nv_bfloat16* __restrict__ Wh, const __nv_bfloat16* __restrict__ Wl,
               const float* __restrict__ bias, float* __restrict__ C,
               __nv_bfloat16* __restrict__ Oh, __nv_bfloat16* __restrict__ Ol,
               int N, int K) {
    extern __shared__ char smem[];
    const uint32_t sb = smem_to_u32(smem);
    int tid = threadIdx.x, lane = tid & 31, warp = tid >> 5;
    int wm = warp >> 1;          // 0..3 -> 32 rows each
    int wn = warp & 1;           // 0..1 -> 32 cols each
    int bm = blockIdx.x * 128, bn = blockIdx.y * 64;

    float acc[2][4][4];
    #pragma unroll
    for (int i = 0; i < 2; i++)
        #pragma unroll
        for (int j = 0; j < 4; j++)
            #pragma unroll
            for (int k = 0; k < 4; k++) acc[i][j][k] = 0.f;

    // cp.async A: row = tid/2 (128 rows), 4 chunks of 16B each half-row
    int arow = tid >> 1;
    int ac0  = (tid & 1) * 4;
    const __nv_bfloat16* gA_h = Ah + (size_t)(bm + arow) * K + ac0 * 8;
    const __nv_bfloat16* gA_l = Al + (size_t)(bm + arow) * K + ac0 * 8;
    uint32_t asrow = (uint32_t)arow * 128;
    int arsw = arow & 7;
    // cp.async W: row = tid/4 (64 rows), 2 chunks each quarter-row
    int wrow = tid >> 2;
    int wc0  = (tid & 3) * 2;
    const __nv_bfloat16* gW_h = Wh + (size_t)(bn + wrow) * K + wc0 * 8;
    const __nv_bfloat16* gW_l = Wl + (size_t)(bn + wrow) * K + wc0 * 8;
    uint32_t wsrow = (uint32_t)wrow * 128;
    int wrsw = wrow & 7;

    // ldmatrix lane constants
    int mat = lane >> 3, r8 = lane & 7;
    int a_kh = mat >> 1;
    uint32_t arowb[2]; int aswz[2];
    #pragma unroll
    for (int ti = 0; ti < 2; ti++) {
        int row = wm*32 + ti*16 + (mat & 1)*8 + r8;
        arowb[ti] = (uint32_t)row * 128;
        aswz[ti]  = row & 7;
    }
    int bl15 = lane & 15;
    int b_kh = bl15 >> 3;
    uint32_t browb[4]; int bswz[4];
    #pragma unroll
    for (int ni = 0; ni < 4; ni++) {
        int row = wn*32 + ni*8 + (bl15 & 7);
        browb[ni] = (uint32_t)row * 128;
        bswz[ni]  = row & 7;
    }

    const int nch = K / KC;
    {
        uint32_t st = sb;
        #pragma unroll
        for (int i = 0; i < 4; i++) {
            int c = ac0 + i;
            uint32_t soff = asrow + (uint32_t)((c ^ arsw) << 4);
            CP_ASYNC16(st + S_AH + soff, gA_h + i*8);
            CP_ASYNC16(st + S_AL + soff, gA_l + i*8);
        }
        #pragma unroll
        for (int i = 0; i < 2; i++) {
            int c = wc0 + i;
            uint32_t soff = wsrow + (uint32_t)((c ^ wrsw) << 4);
            CP_ASYNC16(st + S_WH + soff, gW_h + i*8);
            CP_ASYNC16(st + S_WL + soff, gW_l + i*8);
        }
        CP_COMMIT;
    }

    for (int ch = 0; ch < nch; ch++) {
        if (ch + 1 < nch) {
            uint32_t st = sb + ((ch + 1) & 1) * STG_B;
            int k0 = (ch + 1) * KC;
            #pragma unroll
            for (int i = 0; i < 4; i++) {
                int c = ac0 + i;
                uint32_t soff = asrow + (uint32_t)((c ^ arsw) << 4);
                CP_ASYNC16(st + S_AH + soff, gA_h + k0 + i*8);
                CP_ASYNC16(st + S_AL + soff, gA_l + k0 + i*8);
            }
            #pragma unroll
            for (int i = 0; i < 2; i++) {
                int c = wc0 + i;
                uint32_t soff = wsrow + (uint32_t)((c ^ wrsw) << 4);
                CP_ASYNC16(st + S_WH + soff, gW_h + k0 + i*8);
                CP_ASYNC16(st + S_WL + soff, gW_l + k0 + i*8);
            }
            CP_COMMIT;
            CP_WAIT1;
        } else {
            CP_WAIT0;
        }
        __syncthreads();

        uint32_t stg = sb + (ch & 1) * STG_B;
        #pragma unroll
        for (int ks = 0; ks < 4; ks++) {
            uint32_t ahf[2][4], alf[2][4];
            #pragma unroll
            for (int ti = 0; ti < 2; ti++) {
                uint32_t off = arowb[ti] + (uint32_t)((((ks << 1) | a_kh) ^ aswz[ti]) << 4);
                ldsm4(ahf[ti], stg + S_AH + off);
                ldsm4(alf[ti], stg + S_AL + off);
            }
            uint32_t bhf[4][2], blf[4][2];
            #pragma unroll
            for (int ni = 0; ni < 4; ni++) {
                uint32_t off = browb[ni] + (uint32_t)((((ks << 1) | b_kh) ^ bswz[ni]) << 4);
                ldsm2(bhf[ni], stg + S_WH + off);
                ldsm2(blf[ni], stg + S_WL + off);
            }
            #pragma unroll
            for (int ti = 0; ti < 2; ti++)
                #pragma unroll
                for (int ni = 0; ni < 4; ni++) {
                    mma_bf16(acc[ti][ni], ahf[ti], bhf[ni]);
                    mma_bf16(acc[ti][ni], ahf[ti], blf[ni]);
                    mma_bf16(acc[ti][ni], alf[ti], bhf[ni]);
                }
        }
        __syncthreads();
    }

    int lr = lane >> 2, lc = (lane & 3) * 2;
    #pragma unroll
    for (int ti = 0; ti < 2; ti++) {
        #pragma unroll
        for (int ni = 0; ni < 4; ni++) {
            int grow = bm + wm*32 + ti*16 + lr;
            int gcol = bn + wn*32 + ni*8 + lc;
            #pragma unroll
            for (int half = 0; half < 2; half++) {
                int r = grow + half*8;
                size_t off = (size_t)r * N + gcol;
                float v0 = acc[ti][ni][half*2 + 0];
                float v1 = acc[ti][ni][half*2 + 1];
                if (OP == 0) {
                    *(float2*)&C[off] = make_float2(v0, v1);
                } else if (OP == 1) {
                    *(float2*)&C[off] = make_float2(v0 + bias[gcol], v1 + bias[gcol+1]);
                } else if (OP == 2) {
                    float2 hcur = *(float2*)&C[off];
                    *(float2*)&C[off] = make_float2(v0 + bias[gcol]   + hcur.x,
                                                    v1 + bias[gcol+1] + hcur.y);
                } else {
                    float f0 = fmaxf(v0 + bias[gcol],   0.f);
                    float f1 = fmaxf(v1 + bias[gcol+1], 0.f);
                    __nv_bfloat16 h0 = __float2bfloat16(f0);
                    __nv_bfloat16 h1 = __float2bfloat16(f1);
                    *(__nv_bfloat162*)&Oh[off] = __nv_bfloat162(h0, h1);
                    __nv_bfloat16 l0 = __float2bfloat16(f0 - __bfloat162float(h0));
                    __nv_bfloat16 l1 = __float2bfloat16(f1 - __bfloat162float(h1));
                    *(__nv_bfloat162*)&Ol[off] = __nv_bfloat162(l0, l1);
                }
            }
        }
    }
}

// =============== Causal attention (round-3 validated) ======================
__global__ __launch_bounds__(64)
void attn_kernel(const float* __restrict__ qkv,
                 __nv_bfloat16* __restrict__ oh, __nv_bfloat16* __restrict__ ol) {
    __shared__ float Ks[64][64];
    __shared__ float Vs[64][64];

    int bh = blockIdx.y;
    int b  = bh / HH, h = bh % HH;
    int qb = blockIdx.x;
    int tid = threadIdx.x;
    int tok = b * TT + qb * 64 + tid;

    float4 q4[16];
    const float4* qp = (const float4*)(qkv + (size_t)tok * DQKV + h * HD);
    #pragma unroll
    for (int i = 0; i < 16; i++) {
        q4[i] = qp[i];
        q4[i].x *= 0.125f; q4[i].y *= 0.125f; q4[i].z *= 0.125f; q4[i].w *= 0.125f;
    }
    float4 a4[16];
    #pragma unroll
    for (int i = 0; i < 16; i++) a4[i] = make_float4(0.f, 0.f, 0.f, 0.f);
    float mmax = -INFINITY, lsum = 0.f;

    for (int kt = 0; kt <= qb; kt++) {
        const float* kb = qkv + (size_t)(b*TT + kt*64) * DQKV + DD + h*HD;
        const float* vb = kb + DD;
        __syncthreads();
        for (int j = 0; j < 64; j++) {
            Ks[j][tid] = kb[(size_t)j * DQKV + tid];
            Vs[j][tid] = vb[(size_t)j * DQKV + tid];
        }
        __syncthreads();

        int jmax = (kt == qb) ? (tid + 1) : 64;
        for (int j = 0; j < jmax; j++) {
            const float4* kr = (const float4*)Ks[j];
            float s = 0.f;
            #pragma unroll
            for (int i = 0; i < 16; i++) {
                float4 k = kr[i];
                s += q4[i].x*k.x + q4[i].y*k.y + q4[i].z*k.z + q4[i].w*k.w;
            }
            float p;
            if (s > mmax) {
                float corr = __expf(mmax - s);
                #pragma unroll
                for (int i = 0; i < 16; i++) {
                    a4[i].x *= corr; a4[i].y *= corr; a4[i].z *= corr; a4[i].w *= corr;
                }
                lsum *= corr; mmax = s; p = 1.f;
            } else {
                p = __expf(s - mmax);
            }
            lsum += p;
            const float4* vr = (const float4*)Vs[j];
            #pragma unroll
            for (int i = 0; i < 16; i++) {
                float4 vv = vr[i];
                a4[i].x = fmaf(p, vv.x, a4[i].x);
                a4[i].y = fmaf(p, vv.y, a4[i].y);
                a4[i].z = fmaf(p, vv.z, a4[i].z);
                a4[i].w = fmaf(p, vv.w, a4[i].w);
            }
        }
    }

    float inv = 1.0f / lsum;
    size_t ob = (size_t)tok * DD + h * HD;
    #pragma unroll
    for (int i = 0; i < 16; i++) {
        float f[4] = { a4[i].x*inv, a4[i].y*inv, a4[i].z*inv, a4[i].w*inv };
        #pragma unroll
        for (int c = 0; c < 4; c++) {
            __nv_bfloat16 hh = __float2bfloat16(f[c]);
            oh[ob + i*4 + c] = hh;
            ol[ob + i*4 + c] = __float2bfloat16(f[c] - __bfloat162float(hh));
        }
    }
}

// ---------------- Driver ---------------------------
extern "C" void kernel_launch(void* const* d_in, const int* in_sizes, int n_in,
                              void* d_out, int out_size) {
    (void)in_sizes; (void)n_in; (void)out_size;
    const int*   x       = (const int*)  d_in[0];
    const float* tok_emb = (const float*)d_in[1];
    const float* pos_emb = (const float*)d_in[2];
    const float* qkv_w   = (const float*)d_in[3];
    const float* fc_w    = (const float*)d_in[4];
    const float* fc_b    = (const float*)d_in[5];
    const float* ln1_s   = (const float*)d_in[6];
    const float* ln1_b   = (const float*)d_in[7];
    const float* ln2_s   = (const float*)d_in[8];
    const float* ln2_b   = (const float*)d_in[9];
    const float* ff1_w   = (const float*)d_in[10];
    const float* ff1_b   = (const float*)d_in[11];
    const float* ff2_w   = (const float*)d_in[12];
    const float* ff2_b   = (const float*)d_in[13];
    const float* lnf_s   = (const float*)d_in[14];
    const float* lnf_b   = (const float*)d_in[15];
    const float* out_w   = (const float*)d_in[16];
    const float* out_b   = (const float*)d_in[17];
    float* logits = (float*)d_out;

    cudaFuncSetAttribute(mm_kernel<0>, cudaFuncAttributeMaxDynamicSharedMemorySize, GEMM_SMEM);
    cudaFuncSetAttribute(mm_kernel<1>, cudaFuncAttributeMaxDynamicSharedMemorySize, GEMM_SMEM);
    cudaFuncSetAttribute(mm_kernel<2>, cudaFuncAttributeMaxDynamicSharedMemorySize, GEMM_SMEM);
    cudaFuncSetAttribute(mm_kernel<3>, cudaFuncAttributeMaxDynamicSharedMemorySize, GEMM_SMEM);

    float *h, *qkvb;
    __nv_bfloat16 *xh, *xl, *ah, *al, *fh, *fl;
    __nv_bfloat16 *qh, *ql, *fch, *fcl, *f1h, *f1l, *f2h, *f2l, *oh, *ol;
    cudaGetSymbolAddress((void**)&h,    g_h);
    cudaGetSymbolAddress((void**)&qkvb, g_qkv);
    cudaGetSymbolAddress((void**)&xh, g_xh);  cudaGetSymbolAddress((void**)&xl, g_xl);
    cudaGetSymbolAddress((void**)&ah, g_ah);  cudaGetSymbolAddress((void**)&al, g_al);
    cudaGetSymbolAddress((void**)&fh, g_fh);  cudaGetSymbolAddress((void**)&fl, g_fl);
    cudaGetSymbolAddress((void**)&qh, w_qkvh); cudaGetSymbolAddress((void**)&ql, w_qkvl);
    cudaGetSymbolAddress((void**)&fch, w_fch); cudaGetSymbolAddress((void**)&fcl, w_fcl);
    cudaGetSymbolAddress((void**)&f1h, w_f1h); cudaGetSymbolAddress((void**)&f1l, w_f1l);
    cudaGetSymbolAddress((void**)&f2h, w_f2h); cudaGetSymbolAddress((void**)&f2l, w_f2l);
    cudaGetSymbolAddress((void**)&oh, w_oh);   cudaGetSymbolAddress((void**)&ol, w_ol);

    cvt_kernel<<<2048, 256>>>(qkv_w, qh, ql, LL*DQKV*DD/4);
    cvt_kernel<<<1024, 256>>>(fc_w,  fch, fcl, LL*DD*DD/4);
    cvt_kernel<<<2048, 256>>>(ff1_w, f1h, f1l, LL*DFF*DD/4);
    cvt_kernel<<<2048, 256>>>(ff2_w, f2h, f2l, LL*DD*DFF/4);
    cvt_kernel<<<4096, 256>>>(out_w, oh, ol, VV*DD/4);

    embed_kernel<<<NTOK, 256>>>(x, tok_emb, pos_emb);

    for (int l = 0; l < LL; l++) {
        const __nv_bfloat16* wqh = qh + (size_t)l * DQKV * DD;
        const __nv_bfloat16* wql = ql + (size_t)l * DQKV * DD;
        const __nv_bfloat16* wph = fch + (size_t)l * DD * DD;
        const __nv_bfloat16* wpl = fcl + (size_t)l * DD * DD;
        const __nv_bfloat16* w1h = f1h + (size_t)l * DFF * DD;
        const __nv_bfloat16* w1l = f1l + (size_t)l * DFF * DD;
        const __nv_bfloat16* w2h = f2h + (size_t)l * DD * DFF;
        const __nv_bfloat16* w2l = f2l + (size_t)l * DD * DFF;

        ln_kernel<<<NTOK, 256>>>(h, ln1_s + (size_t)l*DD, ln1_b + (size_t)l*DD, xh, xl);
        mm_kernel<0><<<dim3(NTOK/128, DQKV/64), 256, GEMM_SMEM>>>(
            xh, xl, wqh, wql, nullptr, qkvb, nullptr, nullptr, DQKV, DD);
        attn_kernel<<<dim3(TT/64, BB*HH), 64>>>(qkvb, ah, al);
        mm_kernel<2><<<dim3(NTOK/128, DD/64), 256, GEMM_SMEM>>>(
            ah, al, wph, wpl, fc_b + (size_t)l*DD, h, nullptr, nullptr, DD, DD);
        ln_kernel<<<NTOK, 256>>>(h, ln2_s + (size_t)l*DD, ln2_b + (size_t)l*DD, xh, xl);
        mm_kernel<3><<<dim3(NTOK/128, DFF/64), 256, GEMM_SMEM>>>(
            xh, xl, w1h, w1l, ff1_b + (size_t)l*DFF, nullptr, fh, fl, DFF, DD);
        mm_kernel<2><<<dim3(NTOK/128, DD/64), 256, GEMM_SMEM>>>(
            fh, fl, w2h, w2l, ff2_b + (size_t)l*DD, h, nullptr, nullptr, DD, DFF);
    }

    ln_kernel<<<NTOK, 256>>>(h, lnf_s, lnf_b, xh, xl);
    mm_kernel<1><<<dim3(NTOK/128, VV/64), 256, GEMM_SMEM>>>(
        xh, xl, oh, ol, out_b, logits, nullptr, nullptr, VV, DD);
}

// round 9
// speedup vs baseline: 1.4613x; 1.0100x over previous
#include <cuda_runtime.h>
#include <cuda_bf16.h>
#include <math.h>
#include <stdint.h>

// ---------------- Problem constants ----------------
#define BB    4
#define TT    1024
#define NTOK  (BB*TT)
#define DD    768
#define HH    12
#define HD    64
#define LL    6
#define VV    32000
#define DFF   3072
#define DQKV  2304
#define EPS   1e-5f

// ---------------- Static device buffers ------------
__device__ float g_h   [NTOK * DD];     // residual stream (fp32)
__device__ float g_qkv [NTOK * DQKV];   // qkv projections (fp32)
__device__ __nv_bfloat16 g_xh[NTOK*DD],  g_xl[NTOK*DD];    // LN out hi/lo
__device__ __nv_bfloat16 g_ah[NTOK*DD],  g_al[NTOK*DD];    // attn out hi/lo
__device__ __nv_bfloat16 g_fh[NTOK*DFF], g_fl[NTOK*DFF];   // relu out hi/lo
// bf16 hi/lo weight copies
__device__ __nv_bfloat16 w_qkvh[LL*DQKV*DD], w_qkvl[LL*DQKV*DD];
__device__ __nv_bfloat16 w_fch [LL*DD*DD],   w_fcl [LL*DD*DD];
__device__ __nv_bfloat16 w_f1h [LL*DFF*DD],  w_f1l [LL*DFF*DD];
__device__ __nv_bfloat16 w_f2h [LL*DD*DFF],  w_f2l [LL*DD*DFF];
__device__ __nv_bfloat16 w_oh  [VV*DD],      w_ol  [VV*DD];

// ---------------- PTX helpers (arch-generic only) ---
__device__ __forceinline__ uint32_t smem_to_u32(const void* p) {
    uint32_t a;
    asm("{ .reg .u64 t; cvta.to.shared.u64 t, %1; cvt.u32.u64 %0, t; }"
        : "=r"(a) : "l"(p));
    return a;
}
#define CP_ASYNC16(dst, src) \
    asm volatile("cp.async.cg.shared.global [%0], [%1], 16;" :: "r"(dst), "l"(src))
#define CP_COMMIT asm volatile("cp.async.commit_group;" ::: "memory")
#define CP_WAIT1  asm volatile("cp.async.wait_group 1;" ::: "memory")
#define CP_WAIT0  asm volatile("cp.async.wait_group 0;" ::: "memory")

__device__ __forceinline__ void ldsm4(uint32_t* r, uint32_t addr) {
    asm volatile("ldmatrix.sync.aligned.m8n8.x4.shared.b16 {%0,%1,%2,%3}, [%4];"
        : "=r"(r[0]), "=r"(r[1]), "=r"(r[2]), "=r"(r[3]) : "r"(addr));
}
__device__ __forceinline__ void ldsm2(uint32_t* r, uint32_t addr) {
    asm volatile("ldmatrix.sync.aligned.m8n8.x2.shared.b16 {%0,%1}, [%2];"
        : "=r"(r[0]), "=r"(r[1]) : "r"(addr));
}
__device__ __forceinline__ void mma_bf16(float* d, const uint32_t* a, const uint32_t* b) {
    asm volatile("mma.sync.aligned.m16n8k16.row.col.f32.bf16.bf16.f32 "
        "{%0,%1,%2,%3}, {%4,%5,%6,%7}, {%8,%9}, {%0,%1,%2,%3};"
        : "+f"(d[0]), "+f"(d[1]), "+f"(d[2]), "+f"(d[3])
        : "r"(a[0]), "r"(a[1]), "r"(a[2]), "r"(a[3]), "r"(b[0]), "r"(b[1]));
}

__device__ __forceinline__ float dot4(const float4& a, const float4& b) {
    return fmaf(a.x, b.x, fmaf(a.y, b.y, fmaf(a.z, b.z, a.w * b.w)));
}

// ---------------- Embedding ------------------------
__global__ void embed_kernel(const int* __restrict__ x,
                             const float* __restrict__ tok_emb,
                             const float* __restrict__ pos_emb) {
    int row = blockIdx.x;
    int t   = row % TT;
    int id  = x[row];
    const float* te = tok_emb + (size_t)id * DD;
    const float* pe = pos_emb + (size_t)t  * DD;
    float* out = g_h + (size_t)row * DD;
    for (int i = threadIdx.x; i < DD; i += blockDim.x)
        out[i] = te[i] + pe[i];
}

// ---------------- fp32 -> bf16 hi/lo split ---------
__global__ void cvt_kernel(const float* __restrict__ s,
                           __nv_bfloat16* __restrict__ hi,
                           __nv_bfloat16* __restrict__ lo, int n4) {
    int i = blockIdx.x * blockDim.x + threadIdx.x;
    int stride = gridDim.x * blockDim.x;
    for (; i < n4; i += stride) {
        float4 v = ((const float4*)s)[i];
        __nv_bfloat16 h0 = __float2bfloat16(v.x);
        __nv_bfloat16 h1 = __float2bfloat16(v.y);
        __nv_bfloat16 h2 = __float2bfloat16(v.z);
        __nv_bfloat16 h3 = __float2bfloat16(v.w);
        __nv_bfloat16 l0 = __float2bfloat16(v.x - __bfloat162float(h0));
        __nv_bfloat16 l1 = __float2bfloat16(v.y - __bfloat162float(h1));
        __nv_bfloat16 l2 = __float2bfloat16(v.z - __bfloat162float(h2));
        __nv_bfloat16 l3 = __float2bfloat16(v.w - __bfloat162float(h3));
        __nv_bfloat162* ph = (__nv_bfloat162*)hi + i*2;
        __nv_bfloat162* pl = (__nv_bfloat162*)lo + i*2;
        ph[0] = __nv_bfloat162(h0, h1); ph[1] = __nv_bfloat162(h2, h3);
        pl[0] = __nv_bfloat162(l0, l1); pl[1] = __nv_bfloat162(l2, l3);
    }
}

// ---------------- LayerNorm -> bf16 hi/lo ----------
__device__ __forceinline__ float block_reduce_sum(float v, float* red) {
    int lane = threadIdx.x & 31, wid = threadIdx.x >> 5;
    #pragma unroll
    for (int o = 16; o > 0; o >>= 1) v += __shfl_xor_sync(0xffffffffu, v, o);
    if (lane == 0) red[wid] = v;
    __syncthreads();
    if (wid == 0) {
        float w = (lane < (blockDim.x >> 5)) ? red[lane] : 0.f;
        #pragma unroll
        for (int o = 4; o > 0; o >>= 1) w += __shfl_xor_sync(0xffffffffu, w, o);
        if (lane == 0) red[0] = w;
    }
    __syncthreads();
    float r = red[0];
    __syncthreads();
    return r;
}

__global__ void ln_kernel(const float* __restrict__ xin,
                          const float* __restrict__ sc,
                          const float* __restrict__ bi,
                          __nv_bfloat16* __restrict__ yh,
                          __nv_bfloat16* __restrict__ yl) {
    __shared__ float red[32];
    int row = blockIdx.x;
    const float* xr = xin + (size_t)row * DD;
    float xv[3];
    float s = 0.f;
    #pragma unroll
    for (int i = 0; i < 3; i++) { xv[i] = xr[threadIdx.x + i*256]; s += xv[i]; }
    float mean = block_reduce_sum(s, red) * (1.0f / DD);
    float vs = 0.f;
    #pragma unroll
    for (int i = 0; i < 3; i++) { float d = xv[i] - mean; vs += d * d; }
    float var = block_reduce_sum(vs, red) * (1.0f / DD);
    float rstd = rsqrtf(var + EPS);
    #pragma unroll
    for (int i = 0; i < 3; i++) {
        int c = threadIdx.x + i*256;
        float v = (xv[i] - mean) * rstd * sc[c] + bi[c];
        __nv_bfloat16 h = __float2bfloat16(v);
        yh[(size_t)row*DD + c] = h;
        yl[(size_t)row*DD + c] = __float2bfloat16(v - __bfloat162float(h));
    }
}

// =============== 128x64 HMMA GEMM, 2 CTAs/SM (validated @8.61ms) ===========
#define KC         64
#define S_AH       0
#define S_AL       16384
#define S_WH       32768
#define S_WL       40960
#define STG_B      49152
#define GEMM_SMEM  (2*STG_B)

template<int OP>
__global__ __launch_bounds__(256, 2)
void mm_kernel(const __nv_bfloat16* __restrict__ Ah, const __nv_bfloat16* __restrict__ Al,
               const __nv_bfloat16* __restrict__ Wh, const __nv_bfloat16* __restrict__ Wl,
               const float* __restrict__ bias, float* __restrict__ C,
               __nv_bfloat16* __restrict__ Oh, __nv_bfloat16* __restrict__ Ol,
               int N, int K) {
    extern __shared__ char smem[];
    const uint32_t sb = smem_to_u32(smem);
    int tid = threadIdx.x, lane = tid & 31, warp = tid >> 5;
    int wm = warp >> 1;
    int wn = warp & 1;
    int bm = blockIdx.x * 128, bn = blockIdx.y * 64;

    float acc[2][4][4];
    #pragma unroll
    for (int i = 0; i < 2; i++)
        #pragma unroll
        for (int j = 0; j < 4; j++)
            #pragma unroll
            for (int k = 0; k < 4; k++) acc[i][j][k] = 0.f;

    int arow = tid >> 1;
    int ac0  = (tid & 1) * 4;
    const __nv_bfloat16* gA_h = Ah + (size_t)(bm + arow) * K + ac0 * 8;
    const __nv_bfloat16* gA_l = Al + (size_t)(bm + arow) * K + ac0 * 8;
    uint32_t asrow = (uint32_t)arow * 128;
    int arsw = arow & 7;
    int wrow = tid >> 2;
    int wc0  = (tid & 3) * 2;
    const __nv_bfloat16* gW_h = Wh + (size_t)(bn + wrow) * K + wc0 * 8;
    const __nv_bfloat16* gW_l = Wl + (size_t)(bn + wrow) * K + wc0 * 8;
    uint32_t wsrow = (uint32_t)wrow * 128;
    int wrsw = wrow & 7;

    int mat = lane >> 3, r8 = lane & 7;
    int a_kh = mat >> 1;
    uint32_t arowb[2]; int aswz[2];
    #pragma unroll
    for (int ti = 0; ti < 2; ti++) {
        int row = wm*32 + ti*16 + (mat & 1)*8 + r8;
        arowb[ti] = (uint32_t)row * 128;
        aswz[ti]  = row & 7;
    }
    int bl15 = lane & 15;
    int b_kh = bl15 >> 3;
    uint32_t browb[4]; int bswz[4];
    #pragma unroll
    for (int ni = 0; ni < 4; ni++) {
        int row = wn*32 + ni*8 + (bl15 & 7);
        browb[ni] = (uint32_t)row * 128;
        bswz[ni]  = row & 7;
    }

    const int nch = K / KC;
    {
        uint32_t st = sb;
        #pragma unroll
        for (int i = 0; i < 4; i++) {
            int c = ac0 + i;
            uint32_t soff = asrow + (uint32_t)((c ^ arsw) << 4);
            CP_ASYNC16(st + S_AH + soff, gA_h + i*8);
            CP_ASYNC16(st + S_AL + soff, gA_l + i*8);
        }
        #pragma unroll
        for (int i = 0; i < 2; i++) {
            int c = wc0 + i;
            uint32_t soff = wsrow + (uint32_t)((c ^ wrsw) << 4);
            CP_ASYNC16(st + S_WH + soff, gW_h + i*8);
            CP_ASYNC16(st + S_WL + soff, gW_l + i*8);
        }
        CP_COMMIT;
    }

    for (int ch = 0; ch < nch; ch++) {
        if (ch + 1 < nch) {
            uint32_t st = sb + ((ch + 1) & 1) * STG_B;
            int k0 = (ch + 1) * KC;
            #pragma unroll
            for (int i = 0; i < 4; i++) {
                int c = ac0 + i;
                uint32_t soff = asrow + (uint32_t)((c ^ arsw) << 4);
                CP_ASYNC16(st + S_AH + soff, gA_h + k0 + i*8);
                CP_ASYNC16(st + S_AL + soff, gA_l + k0 + i*8);
            }
            #pragma unroll
            for (int i = 0; i < 2; i++) {
                int c = wc0 + i;
                uint32_t soff = wsrow + (uint32_t)((c ^ wrsw) << 4);
                CP_ASYNC16(st + S_WH + soff, gW_h + k0 + i*8);
                CP_ASYNC16(st + S_WL + soff, gW_l + k0 + i*8);
            }
            CP_COMMIT;
            CP_WAIT1;
        } else {
            CP_WAIT0;
        }
        __syncthreads();

        uint32_t stg = sb + (ch & 1) * STG_B;
        #pragma unroll
        for (int ks = 0; ks < 4; ks++) {
            uint32_t ahf[2][4], alf[2][4];
            #pragma unroll
            for (int ti = 0; ti < 2; ti++) {
                uint32_t off = arowb[ti] + (uint32_t)((((ks << 1) | a_kh) ^ aswz[ti]) << 4);
                ldsm4(ahf[ti], stg + S_AH + off);
                ldsm4(alf[ti], stg + S_AL + off);
            }
            uint32_t bhf[4][2], blf[4][2];
            #pragma unroll
            for (int ni = 0; ni < 4; ni++) {
                uint32_t off = browb[ni] + (uint32_t)((((ks << 1) | b_kh) ^ bswz[ni]) << 4);
                ldsm2(bhf[ni], stg + S_WH + off);
                ldsm2(blf[ni], stg + S_WL + off);
            }
            #pragma unroll
            for (int ti = 0; ti < 2; ti++)
                #pragma unroll
                for (int ni = 0; ni < 4; ni++) {
                    mma_bf16(acc[ti][ni], ahf[ti], bhf[ni]);
                    mma_bf16(acc[ti][ni], ahf[ti], blf[ni]);
                    mma_bf16(acc[ti][ni], alf[ti], bhf[ni]);
                }
        }
        __syncthreads();
    }

    int lr = lane >> 2, lc = (lane & 3) * 2;
    #pragma unroll
    for (int ti = 0; ti < 2; ti++) {
        #pragma unroll
        for (int ni = 0; ni < 4; ni++) {
            int grow = bm + wm*32 + ti*16 + lr;
            int gcol = bn + wn*32 + ni*8 + lc;
            #pragma unroll
            for (int half = 0; half < 2; half++) {
                int r = grow + half*8;
                size_t off = (size_t)r * N + gcol;
                float v0 = acc[ti][ni][half*2 + 0];
                float v1 = acc[ti][ni][half*2 + 1];
                if (OP == 0) {
                    *(float2*)&C[off] = make_float2(v0, v1);
                } else if (OP == 1) {
                    *(float2*)&C[off] = make_float2(v0 + bias[gcol], v1 + bias[gcol+1]);
                } else if (OP == 2) {
                    float2 hcur = *(float2*)&C[off];
                    *(float2*)&C[off] = make_float2(v0 + bias[gcol]   + hcur.x,
                                                    v1 + bias[gcol+1] + hcur.y);
                } else {
                    float f0 = fmaxf(v0 + bias[gcol],   0.f);
                    float f1 = fmaxf(v1 + bias[gcol+1], 0.f);
                    __nv_bfloat16 h0 = __float2bfloat16(f0);
                    __nv_bfloat16 h1 = __float2bfloat16(f1);
                    *(__nv_bfloat162*)&Oh[off] = __nv_bfloat162(h0, h1);
                    __nv_bfloat16 l0 = __float2bfloat16(f0 - __bfloat162float(h0));
                    __nv_bfloat16 l1 = __float2bfloat16(f1 - __bfloat162float(h1));
                    *(__nv_bfloat162*)&Ol[off] = __nv_bfloat162(l0, l1);
                }
            }
        }
    }
}

// =============== Causal attention: ILP-restructured inner loop =============
// Same structure as the validated round-3 kernel (1 q/thread, 64 thr, lazy
// rescale, __expf). Changes: 4-way partial-sum dot (chain 256->~64cyc),
// 2-way j unroll (2 independent score chains), vectorized bf16 stores.
__global__ __launch_bounds__(64)
void attn_kernel(const float* __restrict__ qkv,
                 __nv_bfloat16* __restrict__ oh, __nv_bfloat16* __restrict__ ol) {
    __shared__ float Ks[64][64];
    __shared__ float Vs[64][64];

    int bh = blockIdx.y;
    int b  = bh / HH, h = bh % HH;
    int qb = blockIdx.x;
    int tid = threadIdx.x;
    int tok = b * TT + qb * 64 + tid;

    float4 q4[16];
    const float4* qp = (const float4*)(qkv + (size_t)tok * DQKV + h * HD);
    #pragma unroll
    for (int i = 0; i < 16; i++) {
        q4[i] = qp[i];
        q4[i].x *= 0.125f; q4[i].y *= 0.125f; q4[i].z *= 0.125f; q4[i].w *= 0.125f;
    }
    float4 a4[16];
    #pragma unroll
    for (int i = 0; i < 16; i++) a4[i] = make_float4(0.f, 0.f, 0.f, 0.f);
    float mmax = -INFINITY, lsum = 0.f;

    for (int kt = 0; kt <= qb; kt++) {
        const float* kb = qkv + (size_t)(b*TT + kt*64) * DQKV + DD + h*HD;
        const float* vb = kb + DD;
        __syncthreads();
        for (int j = 0; j < 64; j++) {
            Ks[j][tid] = kb[(size_t)j * DQKV + tid];
            Vs[j][tid] = vb[(size_t)j * DQKV + tid];
        }
        __syncthreads();

        int jmax = (kt == qb) ? (tid + 1) : 64;
        int j = 0;
        // 2-way unrolled main loop: two independent 4-partial score chains
        for (; j + 2 <= jmax; j += 2) {
            const float4* kr0 = (const float4*)Ks[j];
            const float4* kr1 = (const float4*)Ks[j+1];
            float sA = 0.f, sB = 0.f, sC = 0.f, sD = 0.f;
            float tA = 0.f, tB = 0.f, tC = 0.f, tD = 0.f;
            #pragma unroll
            for (int i = 0; i < 16; i += 4) {
                sA += dot4(q4[i+0], kr0[i+0]);
                sB += dot4(q4[i+1], kr0[i+1]);
                sC += dot4(q4[i+2], kr0[i+2]);
                sD += dot4(q4[i+3], kr0[i+3]);
                tA += dot4(q4[i+0], kr1[i+0]);
                tB += dot4(q4[i+1], kr1[i+1]);
                tC += dot4(q4[i+2], kr1[i+2]);
                tD += dot4(q4[i+3], kr1[i+3]);
            }
            float s0 = (sA + sB) + (sC + sD);
            float s1 = (tA + tB) + (tC + tD);

            // --- update with j ---
            float p0;
            if (s0 > mmax) {
                float corr = __expf(mmax - s0);
                #pragma unroll
                for (int i = 0; i < 16; i++) {
                    a4[i].x *= corr; a4[i].y *= corr; a4[i].z *= corr; a4[i].w *= corr;
                }
                lsum *= corr; mmax = s0; p0 = 1.f;
            } else {
                p0 = __expf(s0 - mmax);
            }
            lsum += p0;
            // --- update with j+1 (uses possibly-updated mmax) ---
            float p1;
            if (s1 > mmax) {
                float corr = __expf(mmax - s1);
                #pragma unroll
                for (int i = 0; i < 16; i++) {
                    a4[i].x *= corr; a4[i].y *= corr; a4[i].z *= corr; a4[i].w *= corr;
                }
                lsum *= corr; p0 *= corr; mmax = s1; p1 = 1.f;
            } else {
                p1 = __expf(s1 - mmax);
            }
            lsum += p1;

            const float4* vr0 = (const float4*)Vs[j];
            const float4* vr1 = (const float4*)Vs[j+1];
            #pragma unroll
            for (int i = 0; i < 16; i++) {
                float4 v0 = vr0[i], v1 = vr1[i];
                a4[i].x = fmaf(p0, v0.x, fmaf(p1, v1.x, a4[i].x));
                a4[i].y = fmaf(p0, v0.y, fmaf(p1, v1.y, a4[i].y));
                a4[i].z = fmaf(p0, v0.z, fmaf(p1, v1.z, a4[i].z));
                a4[i].w = fmaf(p0, v0.w, fmaf(p1, v1.w, a4[i].w));
            }
        }
        // tail (0 or 1 iteration)
        for (; j < jmax; j++) {
            const float4* kr = (const float4*)Ks[j];
            float sA = 0.f, sB = 0.f, sC = 0.f, sD = 0.f;
            #pragma unroll
            for (int i = 0; i < 16; i += 4) {
                sA += dot4(q4[i+0], kr[i+0]);
                sB += dot4(q4[i+1], kr[i+1]);
                sC += dot4(q4[i+2], kr[i+2]);
                sD += dot4(q4[i+3], kr[i+3]);
            }
            float s = (sA + sB) + (sC + sD);
            float p;
            if (s > mmax) {
                float corr = __expf(mmax - s);
                #pragma unroll
                for (int i = 0; i < 16; i++) {
                    a4[i].x *= corr; a4[i].y *= corr; a4[i].z *= corr; a4[i].w *= corr;
                }
                lsum *= corr; mmax = s; p = 1.f;
            } else {
                p = __expf(s - mmax);
            }
            lsum += p;
            const float4* vr = (const float4*)Vs[j];
            #pragma unroll
            for (int i = 0; i < 16; i++) {
                float4 vv = vr[i];
                a4[i].x = fmaf(p, vv.x, a4[i].x);
                a4[i].y = fmaf(p, vv.y, a4[i].y);
                a4[i].z = fmaf(p, vv.z, a4[i].z);
                a4[i].w = fmaf(p, vv.w, a4[i].w);
            }
        }
    }

    float inv = 1.0f / lsum;
    size_t ob = (size_t)tok * DD + h * HD;
    #pragma unroll
    for (int i = 0; i < 16; i++) {
        float f0 = a4[i].x*inv, f1 = a4[i].y*inv, f2 = a4[i].z*inv, f3 = a4[i].w*inv;
        __nv_bfloat16 h0 = __float2bfloat16(f0), h1 = __float2bfloat16(f1);
        __nv_bfloat16 h2 = __float2bfloat16(f2), h3 = __float2bfloat16(f3);
        *(__nv_bfloat162*)&oh[ob + i*4 + 0] = __nv_bfloat162(h0, h1);
        *(__nv_bfloat162*)&oh[ob + i*4 + 2] = __nv_bfloat162(h2, h3);
        __nv_bfloat16 l0 = __float2bfloat16(f0 - __bfloat162float(h0));
        __nv_bfloat16 l1 = __float2bfloat16(f1 - __bfloat162float(h1));
        __nv_bfloat16 l2 = __float2bfloat16(f2 - __bfloat162float(h2));
        __nv_bfloat16 l3 = __float2bfloat16(f3 - __bfloat162float(h3));
        *(__nv_bfloat162*)&ol[ob + i*4 + 0] = __nv_bfloat162(l0, l1);
        *(__nv_bfloat162*)&ol[ob + i*4 + 2] = __nv_bfloat162(l2, l3);
    }
}

// ---------------- Driver ---------------------------
extern "C" void kernel_launch(void* const* d_in, const int* in_sizes, int n_in,
                              void* d_out, int out_size) {
    (void)in_sizes; (void)n_in; (void)out_size;
    const int*   x       = (const int*)  d_in[0];
    const float* tok_emb = (const float*)d_in[1];
    const float* pos_emb = (const float*)d_in[2];
    const float* qkv_w   = (const float*)d_in[3];
    const float* fc_w    = (const float*)d_in[4];
    const float* fc_b    = (const float*)d_in[5];
    const float* ln1_s   = (const float*)d_in[6];
    const float* ln1_b   = (const float*)d_in[7];
    const float* ln2_s   = (const float*)d_in[8];
    const float* ln2_b   = (const float*)d_in[9];
    const float* ff1_w   = (const float*)d_in[10];
    const float* ff1_b   = (const float*)d_in[11];
    const float* ff2_w   = (const float*)d_in[12];
    const float* ff2_b   = (const float*)d_in[13];
    const float* lnf_s   = (const float*)d_in[14];
    const float* lnf_b   = (const float*)d_in[15];
    const float* out_w   = (const float*)d_in[16];
    const float* out_b   = (const float*)d_in[17];
    float* logits = (float*)d_out;

    cudaFuncSetAttribute(mm_kernel<0>, cudaFuncAttributeMaxDynamicSharedMemorySize, GEMM_SMEM);
    cudaFuncSetAttribute(mm_kernel<1>, cudaFuncAttributeMaxDynamicSharedMemorySize, GEMM_SMEM);
    cudaFuncSetAttribute(mm_kernel<2>, cudaFuncAttributeMaxDynamicSharedMemorySize, GEMM_SMEM);
    cudaFuncSetAttribute(mm_kernel<3>, cudaFuncAttributeMaxDynamicSharedMemorySize, GEMM_SMEM);

    float *h, *qkvb;
    __nv_bfloat16 *xh, *xl, *ah, *al, *fh, *fl;
    __nv_bfloat16 *qh, *ql, *fch, *fcl, *f1h, *f1l, *f2h, *f2l, *oh, *ol;
    cudaGetSymbolAddress((void**)&h,    g_h);
    cudaGetSymbolAddress((void**)&qkvb, g_qkv);
    cudaGetSymbolAddress((void**)&xh, g_xh);  cudaGetSymbolAddress((void**)&xl, g_xl);
    cudaGetSymbolAddress((void**)&ah, g_ah);  cudaGetSymbolAddress((void**)&al, g_al);
    cudaGetSymbolAddress((void**)&fh, g_fh);  cudaGetSymbolAddress((void**)&fl, g_fl);
    cudaGetSymbolAddress((void**)&qh, w_qkvh); cudaGetSymbolAddress((void**)&ql, w_qkvl);
    cudaGetSymbolAddress((void**)&fch, w_fch); cudaGetSymbolAddress((void**)&fcl, w_fcl);
    cudaGetSymbolAddress((void**)&f1h, w_f1h); cudaGetSymbolAddress((void**)&f1l, w_f1l);
    cudaGetSymbolAddress((void**)&f2h, w_f2h); cudaGetSymbolAddress((void**)&f2l, w_f2l);
    cudaGetSymbolAddress((void**)&oh, w_oh);   cudaGetSymbolAddress((void**)&ol, w_ol);

    cvt_kernel<<<2048, 256>>>(qkv_w, qh, ql, LL*DQKV*DD/4);
    cvt_kernel<<<1024, 256>>>(fc_w,  fch, fcl, LL*DD*DD/4);
    cvt_kernel<<<2048, 256>>>(ff1_w, f1h, f1l, LL*DFF*DD/4);
    cvt_kernel<<<2048, 256>>>(ff2_w, f2h, f2l, LL*DD*DFF/4);
    cvt_kernel<<<4096, 256>>>(out_w, oh, ol, VV*DD/4);

    embed_kernel<<<NTOK, 256>>>(x, tok_emb, pos_emb);

    for (int l = 0; l < LL; l++) {
        const __nv_bfloat16* wqh = qh + (size_t)l * DQKV * DD;
        const __nv_bfloat16* wql = ql + (size_t)l * DQKV * DD;
        const __nv_bfloat16* wph = fch + (size_t)l * DD * DD;
        const __nv_bfloat16* wpl = fcl + (size_t)l * DD * DD;
        const __nv_bfloat16* w1h = f1h + (size_t)l * DFF * DD;
        const __nv_bfloat16* w1l = f1l + (size_t)l * DFF * DD;
        const __nv_bfloat16* w2h = f2h + (size_t)l * DD * DFF;
        const __nv_bfloat16* w2l = f2l + (size_t)l * DD * DFF;

        ln_kernel<<<NTOK, 256>>>(h, ln1_s + (size_t)l*DD, ln1_b + (size_t)l*DD, xh, xl);
        mm_kernel<0><<<dim3(NTOK/128, DQKV/64), 256, GEMM_SMEM>>>(
            xh, xl, wqh, wql, nullptr, qkvb, nullptr, nullptr, DQKV, DD);
        attn_kernel<<<dim3(TT/64, BB*HH), 64>>>(qkvb, ah, al);
        mm_kernel<2><<<dim3(NTOK/128, DD/64), 256, GEMM_SMEM>>>(
            ah, al, wph, wpl, fc_b + (size_t)l*DD, h, nullptr, nullptr, DD, DD);
        ln_kernel<<<NTOK, 256>>>(h, ln2_s + (size_t)l*DD, ln2_b + (size_t)l*DD, xh, xl);
        mm_kernel<3><<<dim3(NTOK/128, DFF/64), 256, GEMM_SMEM>>>(
            xh, xl, w1h, w1l, ff1_b + (size_t)l*DFF, nullptr, fh, fl, DFF, DD);
        mm_kernel<2><<<dim3(NTOK/128, DD/64), 256, GEMM_SMEM>>>(
            fh, fl, w2h, w2l, ff2_b + (size_t)l*DD, h, nullptr, nullptr, DD, DFF);
    }

    ln_kernel<<<NTOK, 256>>>(h, lnf_s, lnf_b, xh, xl);
    mm_kernel<1><<<dim3(NTOK/128, VV/64), 256, GEMM_SMEM>>>(
        xh, xl, oh, ol, out_b, logits, nullptr, nullptr, VV, DD);
}

// round 10
// speedup vs baseline: 1.5976x; 1.0932x over previous
#include <cuda_runtime.h>
#include <cuda_bf16.h>
#include <math.h>
#include <stdint.h>

// ---------------- Problem constants ----------------
#define BB    4
#define TT    1024
#define NTOK  (BB*TT)
#define DD    768
#define HH    12
#define HD    64
#define LL    6
#define VV    32000
#define DFF   3072
#define DQKV  2304
#define EPS   1e-5f
#define NSPLIT 4

// ---------------- Static device buffers ------------
__device__ float g_h   [NTOK * DD];     // residual stream (fp32)
__device__ float g_qkv [NTOK * DQKV];   // qkv projections (fp32)
__device__ __nv_bfloat16 g_xh[NTOK*DD],  g_xl[NTOK*DD];    // LN out hi/lo
__device__ __nv_bfloat16 g_ah[NTOK*DD],  g_al[NTOK*DD];    // attn out hi/lo
__device__ __nv_bfloat16 g_fh[NTOK*DFF], g_fl[NTOK*DFF];   // relu out hi/lo
// flash-decoding partials
__device__ float g_pacc[(size_t)NSPLIT * NTOK * DD];
__device__ float g_pm  [(size_t)NSPLIT * NTOK * HH];
__device__ float g_pl  [(size_t)NSPLIT * NTOK * HH];
// bf16 hi/lo weight copies
__device__ __nv_bfloat16 w_qkvh[LL*DQKV*DD], w_qkvl[LL*DQKV*DD];
__device__ __nv_bfloat16 w_fch [LL*DD*DD],   w_fcl [LL*DD*DD];
__device__ __nv_bfloat16 w_f1h [LL*DFF*DD],  w_f1l [LL*DFF*DD];
__device__ __nv_bfloat16 w_f2h [LL*DD*DFF],  w_f2l [LL*DD*DFF];
__device__ __nv_bfloat16 w_oh  [VV*DD],      w_ol  [VV*DD];

// ---------------- PTX helpers (arch-generic only) ---
__device__ __forceinline__ uint32_t smem_to_u32(const void* p) {
    uint32_t a;
    asm("{ .reg .u64 t; cvta.to.shared.u64 t, %1; cvt.u32.u64 %0, t; }"
        : "=r"(a) : "l"(p));
    return a;
}
#define CP_ASYNC16(dst, src) \
    asm volatile("cp.async.cg.shared.global [%0], [%1], 16;" :: "r"(dst), "l"(src))
#define CP_COMMIT asm volatile("cp.async.commit_group;" ::: "memory")
#define CP_WAIT1  asm volatile("cp.async.wait_group 1;" ::: "memory")
#define CP_WAIT0  asm volatile("cp.async.wait_group 0;" ::: "memory")

__device__ __forceinline__ void ldsm4(uint32_t* r, uint32_t addr) {
    asm volatile("ldmatrix.sync.aligned.m8n8.x4.shared.b16 {%0,%1,%2,%3}, [%4];"
        : "=r"(r[0]), "=r"(r[1]), "=r"(r[2]), "=r"(r[3]) : "r"(addr));
}
__device__ __forceinline__ void ldsm2(uint32_t* r, uint32_t addr) {
    asm volatile("ldmatrix.sync.aligned.m8n8.x2.shared.b16 {%0,%1}, [%2];"
        : "=r"(r[0]), "=r"(r[1]) : "r"(addr));
}
__device__ __forceinline__ void mma_bf16(float* d, const uint32_t* a, const uint32_t* b) {
    asm volatile("mma.sync.aligned.m16n8k16.row.col.f32.bf16.bf16.f32 "
        "{%0,%1,%2,%3}, {%4,%5,%6,%7}, {%8,%9}, {%0,%1,%2,%3};"
        : "+f"(d[0]), "+f"(d[1]), "+f"(d[2]), "+f"(d[3])
        : "r"(a[0]), "r"(a[1]), "r"(a[2]), "r"(a[3]), "r"(b[0]), "r"(b[1]));
}

__device__ __forceinline__ float dot4(const float4& a, const float4& b) {
    return fmaf(a.x, b.x, fmaf(a.y, b.y, fmaf(a.z, b.z, a.w * b.w)));
}

// ---------------- Embedding ------------------------
__global__ void embed_kernel(const int* __restrict__ x,
                             const float* __restrict__ tok_emb,
                             const float* __restrict__ pos_emb) {
    int row = blockIdx.x;
    int t   = row % TT;
    int id  = x[row];
    const float* te = tok_emb + (size_t)id * DD;
    const float* pe = pos_emb + (size_t)t  * DD;
    float* out = g_h + (size_t)row * DD;
    for (int i = threadIdx.x; i < DD; i += blockDim.x)
        out[i] = te[i] + pe[i];
}

// ---------------- fp32 -> bf16 hi/lo split ---------
__global__ void cvt_kernel(const float* __restrict__ s,
                           __nv_bfloat16* __restrict__ hi,
                           __nv_bfloat16* __restrict__ lo, int n4) {
    int i = blockIdx.x * blockDim.x + threadIdx.x;
    int stride = gridDim.x * blockDim.x;
    for (; i < n4; i += stride) {
        float4 v = ((const float4*)s)[i];
        __nv_bfloat16 h0 = __float2bfloat16(v.x);
        __nv_bfloat16 h1 = __float2bfloat16(v.y);
        __nv_bfloat16 h2 = __float2bfloat16(v.z);
        __nv_bfloat16 h3 = __float2bfloat16(v.w);
        __nv_bfloat16 l0 = __float2bfloat16(v.x - __bfloat162float(h0));
        __nv_bfloat16 l1 = __float2bfloat16(v.y - __bfloat162float(h1));
        __nv_bfloat16 l2 = __float2bfloat16(v.z - __bfloat162float(h2));
        __nv_bfloat16 l3 = __float2bfloat16(v.w - __bfloat162float(h3));
        __nv_bfloat162* ph = (__nv_bfloat162*)hi + i*2;
        __nv_bfloat162* pl = (__nv_bfloat162*)lo + i*2;
        ph[0] = __nv_bfloat162(h0, h1); ph[1] = __nv_bfloat162(h2, h3);
        pl[0] = __nv_bfloat162(l0, l1); pl[1] = __nv_bfloat162(l2, l3);
    }
}

// ---------------- LayerNorm -> bf16 hi/lo ----------
__device__ __forceinline__ float block_reduce_sum(float v, float* red) {
    int lane = threadIdx.x & 31, wid = threadIdx.x >> 5;
    #pragma unroll
    for (int o = 16; o > 0; o >>= 1) v += __shfl_xor_sync(0xffffffffu, v, o);
    if (lane == 0) red[wid] = v;
    __syncthreads();
    if (wid == 0) {
        float w = (lane < (blockDim.x >> 5)) ? red[lane] : 0.f;
        #pragma unroll
        for (int o = 4; o > 0; o >>= 1) w += __shfl_xor_sync(0xffffffffu, w, o);
        if (lane == 0) red[0] = w;
    }
    __syncthreads();
    float r = red[0];
    __syncthreads();
    return r;
}

__global__ void ln_kernel(const float* __restrict__ xin,
                          const float* __restrict__ sc,
                          const float* __restrict__ bi,
                          __nv_bfloat16* __restrict__ yh,
                          __nv_bfloat16* __restrict__ yl) {
    __shared__ float red[32];
    int row = blockIdx.x;
    const float* xr = xin + (size_t)row * DD;
    float xv[3];
    float s = 0.f;
    #pragma unroll
    for (int i = 0; i < 3; i++) { xv[i] = xr[threadIdx.x + i*256]; s += xv[i]; }
    float mean = block_reduce_sum(s, red) * (1.0f / DD);
    float vs = 0.f;
    #pragma unroll
    for (int i = 0; i < 3; i++) { float d = xv[i] - mean; vs += d * d; }
    float var = block_reduce_sum(vs, red) * (1.0f / DD);
    float rstd = rsqrtf(var + EPS);
    #pragma unroll
    for (int i = 0; i < 3; i++) {
        int c = threadIdx.x + i*256;
        float v = (xv[i] - mean) * rstd * sc[c] + bi[c];
        __nv_bfloat16 h = __float2bfloat16(v);
        yh[(size_t)row*DD + c] = h;
        yl[(size_t)row*DD + c] = __float2bfloat16(v - __bfloat162float(h));
    }
}

// =============== 128x64 HMMA GEMM, 2 CTAs/SM (validated @8.52ms) ===========
#define KC         64
#define S_AH       0
#define S_AL       16384
#define S_WH       32768
#define S_WL       40960
#define STG_B      49152
#define GEMM_SMEM  (2*STG_B)

template<int OP>
__global__ __launch_bounds__(256, 2)
void mm_kernel(const __nv_bfloat16* __restrict__ Ah, const __nv_bfloat16* __restrict__ Al,
               const __nv_bfloat16* __restrict__ Wh, const __nv_bfloat16* __restrict__ Wl,
               const float* __restrict__ bias, float* __restrict__ C,
               __nv_bfloat16* __restrict__ Oh, __nv_bfloat16* __restrict__ Ol,
               int N, int K) {
    extern __shared__ char smem[];
    const uint32_t sb = smem_to_u32(smem);
    int tid = threadIdx.x, lane = tid & 31, warp = tid >> 5;
    int wm = warp >> 1;
    int wn = warp & 1;
    int bm = blockIdx.x * 128, bn = blockIdx.y * 64;

    float acc[2][4][4];
    #pragma unroll
    for (int i = 0; i < 2; i++)
        #pragma unroll
        for (int j = 0; j < 4; j++)
            #pragma unroll
            for (int k = 0; k < 4; k++) acc[i][j][k] = 0.f;

    int arow = tid >> 1;
    int ac0  = (tid & 1) * 4;
    const __nv_bfloat16* gA_h = Ah + (size_t)(bm + arow) * K + ac0 * 8;
    const __nv_bfloat16* gA_l = Al + (size_t)(bm + arow) * K + ac0 * 8;
    uint32_t asrow = (uint32_t)arow * 128;
    int arsw = arow & 7;
    int wrow = tid >> 2;
    int wc0  = (tid & 3) * 2;
    const __nv_bfloat16* gW_h = Wh + (size_t)(bn + wrow) * K + wc0 * 8;
    const __nv_bfloat16* gW_l = Wl + (size_t)(bn + wrow) * K + wc0 * 8;
    uint32_t wsrow = (uint32_t)wrow * 128;
    int wrsw = wrow & 7;

    int mat = lane >> 3, r8 = lane & 7;
    int a_kh = mat >> 1;
    uint32_t arowb[2]; int aswz[2];
    #pragma unroll
    for (int ti = 0; ti < 2; ti++) {
        int row = wm*32 + ti*16 + (mat & 1)*8 + r8;
        arowb[ti] = (uint32_t)row * 128;
        aswz[ti]  = row & 7;
    }
    int bl15 = lane & 15;
    int b_kh = bl15 >> 3;
    uint32_t browb[4]; int bswz[4];
    #pragma unroll
    for (int ni = 0; ni < 4; ni++) {
        int row = wn*32 + ni*8 + (bl15 & 7);
        browb[ni] = (uint32_t)row * 128;
        bswz[ni]  = row & 7;
    }

    const int nch = K / KC;
    {
        uint32_t st = sb;
        #pragma unroll
        for (int i = 0; i < 4; i++) {
            int c = ac0 + i;
            uint32_t soff = asrow + (uint32_t)((c ^ arsw) << 4);
            CP_ASYNC16(st + S_AH + soff, gA_h + i*8);
            CP_ASYNC16(st + S_AL + soff, gA_l + i*8);
        }
        #pragma unroll
        for (int i = 0; i < 2; i++) {
            int c = wc0 + i;
            uint32_t soff = wsrow + (uint32_t)((c ^ wrsw) << 4);
            CP_ASYNC16(st + S_WH + soff, gW_h + i*8);
            CP_ASYNC16(st + S_WL + soff, gW_l + i*8);
        }
        CP_COMMIT;
    }

    for (int ch = 0; ch < nch; ch++) {
        if (ch + 1 < nch) {
            uint32_t st = sb + ((ch + 1) & 1) * STG_B;
            int k0 = (ch + 1) * KC;
            #pragma unroll
            for (int i = 0; i < 4; i++) {
                int c = ac0 + i;
                uint32_t soff = asrow + (uint32_t)((c ^ arsw) << 4);
                CP_ASYNC16(st + S_AH + soff, gA_h + k0 + i*8);
                CP_ASYNC16(st + S_AL + soff, gA_l + k0 + i*8);
            }
            #pragma unroll
            for (int i = 0; i < 2; i++) {
                int c = wc0 + i;
                uint32_t soff = wsrow + (uint32_t)((c ^ wrsw) << 4);
                CP_ASYNC16(st + S_WH + soff, gW_h + k0 + i*8);
                CP_ASYNC16(st + S_WL + soff, gW_l + k0 + i*8);
            }
            CP_COMMIT;
            CP_WAIT1;
        } else {
            CP_WAIT0;
        }
        __syncthreads();

        uint32_t stg = sb + (ch & 1) * STG_B;
        #pragma unroll
        for (int ks = 0; ks < 4; ks++) {
            uint32_t ahf[2][4], alf[2][4];
            #pragma unroll
            for (int ti = 0; ti < 2; ti++) {
                uint32_t off = arowb[ti] + (uint32_t)((((ks << 1) | a_kh) ^ aswz[ti]) << 4);
                ldsm4(ahf[ti], stg + S_AH + off);
                ldsm4(alf[ti], stg + S_AL + off);
            }
            uint32_t bhf[4][2], blf[4][2];
            #pragma unroll
            for (int ni = 0; ni < 4; ni++) {
                uint32_t off = browb[ni] + (uint32_t)((((ks << 1) | b_kh) ^ bswz[ni]) << 4);
                ldsm2(bhf[ni], stg + S_WH + off);
                ldsm2(blf[ni], stg + S_WL + off);
            }
            #pragma unroll
            for (int ti = 0; ti < 2; ti++)
                #pragma unroll
                for (int ni = 0; ni < 4; ni++) {
                    mma_bf16(acc[ti][ni], ahf[ti], bhf[ni]);
                    mma_bf16(acc[ti][ni], ahf[ti], blf[ni]);
                    mma_bf16(acc[ti][ni], alf[ti], bhf[ni]);
                }
        }
        __syncthreads();
    }

    int lr = lane >> 2, lc = (lane & 3) * 2;
    #pragma unroll
    for (int ti = 0; ti < 2; ti++) {
        #pragma unroll
        for (int ni = 0; ni < 4; ni++) {
            int grow = bm + wm*32 + ti*16 + lr;
            int gcol = bn + wn*32 + ni*8 + lc;
            #pragma unroll
            for (int half = 0; half < 2; half++) {
                int r = grow + half*8;
                size_t off = (size_t)r * N + gcol;
                float v0 = acc[ti][ni][half*2 + 0];
                float v1 = acc[ti][ni][half*2 + 1];
                if (OP == 0) {
                    *(float2*)&C[off] = make_float2(v0, v1);
                } else if (OP == 1) {
                    *(float2*)&C[off] = make_float2(v0 + bias[gcol], v1 + bias[gcol+1]);
                } else if (OP == 2) {
                    float2 hcur = *(float2*)&C[off];
                    *(float2*)&C[off] = make_float2(v0 + bias[gcol]   + hcur.x,
                                                    v1 + bias[gcol+1] + hcur.y);
                } else {
                    float f0 = fmaxf(v0 + bias[gcol],   0.f);
                    float f1 = fmaxf(v1 + bias[gcol+1], 0.f);
                    __nv_bfloat16 h0 = __float2bfloat16(f0);
                    __nv_bfloat16 h1 = __float2bfloat16(f1);
                    *(__nv_bfloat162*)&Oh[off] = __nv_bfloat162(h0, h1);
                    __nv_bfloat16 l0 = __float2bfloat16(f0 - __bfloat162float(h0));
                    __nv_bfloat16 l1 = __float2bfloat16(f1 - __bfloat162float(h1));
                    *(__nv_bfloat162*)&Ol[off] = __nv_bfloat162(l0, l1);
                }
            }
        }
    }
}

// =============== Causal attention: flash-decoding split (S=4) ==============
// grid (T/64, B*H, NSPLIT); split s handles K-tiles {s, s+NSPLIT, ...}.
// Writes raw partial acc + (m, l) to scratch; merge kernel combines.
__global__ __launch_bounds__(64)
void attn_kernel(const float* __restrict__ qkv,
                 float* __restrict__ pacc, float* __restrict__ pm,
                 float* __restrict__ pl) {
    __shared__ float Ks[64][64];
    __shared__ float Vs[64][64];

    int bh = blockIdx.y;
    int b  = bh / HH, h = bh % HH;
    int qb = blockIdx.x;
    int sp = blockIdx.z;
    int tid = threadIdx.x;
    int tok = b * TT + qb * 64 + tid;

    float4 a4[16];
    #pragma unroll
    for (int i = 0; i < 16; i++) a4[i] = make_float4(0.f, 0.f, 0.f, 0.f);
    float mmax = -1e30f, lsum = 0.f;

    if (sp <= qb) {
        float4 q4[16];
        const float4* qp = (const float4*)(qkv + (size_t)tok * DQKV + h * HD);
        #pragma unroll
        for (int i = 0; i < 16; i++) {
            q4[i] = qp[i];
            q4[i].x *= 0.125f; q4[i].y *= 0.125f; q4[i].z *= 0.125f; q4[i].w *= 0.125f;
        }

        for (int kt = sp; kt <= qb; kt += NSPLIT) {
            const float* kb = qkv + (size_t)(b*TT + kt*64) * DQKV + DD + h*HD;
            const float* vb = kb + DD;
            __syncthreads();
            for (int j = 0; j < 64; j++) {
                Ks[j][tid] = kb[(size_t)j * DQKV + tid];
                Vs[j][tid] = vb[(size_t)j * DQKV + tid];
            }
            __syncthreads();

            int jmax = (kt == qb) ? (tid + 1) : 64;
            int j = 0;
            for (; j + 2 <= jmax; j += 2) {
                const float4* kr0 = (const float4*)Ks[j];
                const float4* kr1 = (const float4*)Ks[j+1];
                float sA = 0.f, sB = 0.f, sC = 0.f, sD = 0.f;
                float tA = 0.f, tB = 0.f, tC = 0.f, tD = 0.f;
                #pragma unroll
                for (int i = 0; i < 16; i += 4) {
                    sA += dot4(q4[i+0], kr0[i+0]);
                    sB += dot4(q4[i+1], kr0[i+1]);
                    sC += dot4(q4[i+2], kr0[i+2]);
                    sD += dot4(q4[i+3], kr0[i+3]);
                    tA += dot4(q4[i+0], kr1[i+0]);
                    tB += dot4(q4[i+1], kr1[i+1]);
                    tC += dot4(q4[i+2], kr1[i+2]);
                    tD += dot4(q4[i+3], kr1[i+3]);
                }
                float s0 = (sA + sB) + (sC + sD);
                float s1 = (tA + tB) + (tC + tD);

                float p0;
                if (s0 > mmax) {
                    float corr = __expf(mmax - s0);
                    #pragma unroll
                    for (int i = 0; i < 16; i++) {
                        a4[i].x *= corr; a4[i].y *= corr; a4[i].z *= corr; a4[i].w *= corr;
                    }
                    lsum *= corr; mmax = s0; p0 = 1.f;
                } else {
                    p0 = __expf(s0 - mmax);
                }
                lsum += p0;
                float p1;
                if (s1 > mmax) {
                    float corr = __expf(mmax - s1);
                    #pragma unroll
                    for (int i = 0; i < 16; i++) {
                        a4[i].x *= corr; a4[i].y *= corr; a4[i].z *= corr; a4[i].w *= corr;
                    }
                    lsum *= corr; p0 *= corr; mmax = s1; p1 = 1.f;
                } else {
                    p1 = __expf(s1 - mmax);
                }
                lsum += p1;

                const float4* vr0 = (const float4*)Vs[j];
                const float4* vr1 = (const float4*)Vs[j+1];
                #pragma unroll
                for (int i = 0; i < 16; i++) {
                    float4 v0 = vr0[i], v1 = vr1[i];
                    a4[i].x = fmaf(p0, v0.x, fmaf(p1, v1.x, a4[i].x));
                    a4[i].y = fmaf(p0, v0.y, fmaf(p1, v1.y, a4[i].y));
                    a4[i].z = fmaf(p0, v0.z, fmaf(p1, v1.z, a4[i].z));
                    a4[i].w = fmaf(p0, v0.w, fmaf(p1, v1.w, a4[i].w));
                }
            }
            for (; j < jmax; j++) {
                const float4* kr = (const float4*)Ks[j];
                float sA = 0.f, sB = 0.f, sC = 0.f, sD = 0.f;
                #pragma unroll
                for (int i = 0; i < 16; i += 4) {
                    sA += dot4(q4[i+0], kr[i+0]);
                    sB += dot4(q4[i+1], kr[i+1]);
                    sC += dot4(q4[i+2], kr[i+2]);
                    sD += dot4(q4[i+3], kr[i+3]);
                }
                float s = (sA + sB) + (sC + sD);
                float p;
                if (s > mmax) {
                    float corr = __expf(mmax - s);
                    #pragma unroll
                    for (int i = 0; i < 16; i++) {
                        a4[i].x *= corr; a4[i].y *= corr; a4[i].z *= corr; a4[i].w *= corr;
                    }
                    lsum *= corr; mmax = s; p = 1.f;
                } else {
                    p = __expf(s - mmax);
                }
                lsum += p;
                const float4* vr = (const float4*)Vs[j];
                #pragma unroll
                for (int i = 0; i < 16; i++) {
                    float4 vv = vr[i];
                    a4[i].x = fmaf(p, vv.x, a4[i].x);
                    a4[i].y = fmaf(p, vv.y, a4[i].y);
                    a4[i].z = fmaf(p, vv.z, a4[i].z);
                    a4[i].w = fmaf(p, vv.w, a4[i].w);
                }
            }
        }
    }

    // store raw partials
    size_t ab = ((size_t)sp * NTOK + tok) * DD + h * HD;
    #pragma unroll
    for (int i = 0; i < 16; i++)
        *(float4*)&pacc[ab + i*4] = a4[i];
    size_t mi = ((size_t)sp * NTOK + tok) * HH + h;
    pm[mi] = mmax;
    pl[mi] = lsum;
}

// Merge NSPLIT partials -> bf16 hi/lo attention output.
// grid = NTOK*HH blocks of 64 threads (thread = dim).
__global__ __launch_bounds__(64)
void attn_merge(const float* __restrict__ pacc, const float* __restrict__ pm,
                const float* __restrict__ pl,
                __nv_bfloat16* __restrict__ oh, __nv_bfloat16* __restrict__ ol) {
    int tokh = blockIdx.x;
    int tok = tokh / HH, h = tokh % HH;
    int d = threadIdx.x;

    float m[NSPLIT], l[NSPLIT];
    float M = -1e30f;
    #pragma unroll
    for (int s = 0; s < NSPLIT; s++) {
        size_t mi = ((size_t)s * NTOK + tok) * HH + h;
        m[s] = pm[mi]; l[s] = pl[mi];
        M = fmaxf(M, m[s]);
    }
    float L = 0.f, w[NSPLIT];
    #pragma unroll
    for (int s = 0; s < NSPLIT; s++) {
        w[s] = __expf(m[s] - M);
        L = fmaf(l[s], w[s], L);
    }
    float v = 0.f;
    #pragma unroll
    for (int s = 0; s < NSPLIT; s++) {
        size_t ab = ((size_t)s * NTOK + tok) * DD + h * HD + d;
        v = fmaf(pacc[ab], w[s], v);
    }
    float f = v / L;
    size_t ob = (size_t)tok * DD + h * HD + d;
    __nv_bfloat16 hh = __float2bfloat16(f);
    oh[ob] = hh;
    ol[ob] = __float2bfloat16(f - __bfloat162float(hh));
}

// ---------------- Driver ---------------------------
extern "C" void kernel_launch(void* const* d_in, const int* in_sizes, int n_in,
                              void* d_out, int out_size) {
    (void)in_sizes; (void)n_in; (void)out_size;
    const int*   x       = (const int*)  d_in[0];
    const float* tok_emb = (const float*)d_in[1];
    const float* pos_emb = (const float*)d_in[2];
    const float* qkv_w   = (const float*)d_in[3];
    const float* fc_w    = (const float*)d_in[4];
    const float* fc_b    = (const float*)d_in[5];
    const float* ln1_s   = (const float*)d_in[6];
    const float* ln1_b   = (const float*)d_in[7];
    const float* ln2_s   = (const float*)d_in[8];
    const float* ln2_b   = (const float*)d_in[9];
    const float* ff1_w   = (const float*)d_in[10];
    const float* ff1_b   = (const float*)d_in[11];
    const float* ff2_w   = (const float*)d_in[12];
    const float* ff2_b   = (const float*)d_in[13];
    const float* lnf_s   = (const float*)d_in[14];
    const float* lnf_b   = (const float*)d_in[15];
    const float* out_w   = (const float*)d_in[16];
    const float* out_b   = (const float*)d_in[17];
    float* logits = (float*)d_out;

    cudaFuncSetAttribute(mm_kernel<0>, cudaFuncAttributeMaxDynamicSharedMemorySize, GEMM_SMEM);
    cudaFuncSetAttribute(mm_kernel<1>, cudaFuncAttributeMaxDynamicSharedMemorySize, GEMM_SMEM);
    cudaFuncSetAttribute(mm_kernel<2>, cudaFuncAttributeMaxDynamicSharedMemorySize, GEMM_SMEM);
    cudaFuncSetAttribute(mm_kernel<3>, cudaFuncAttributeMaxDynamicSharedMemorySize, GEMM_SMEM);

    float *h, *qkvb, *pacc, *pmv, *plv;
    __nv_bfloat16 *xh, *xl, *ah, *al, *fh, *fl;
    __nv_bfloat16 *qh, *ql, *fch, *fcl, *f1h, *f1l, *f2h, *f2l, *oh, *ol;
    cudaGetSymbolAddress((void**)&h,    g_h);
    cudaGetSymbolAddress((void**)&qkvb, g_qkv);
    cudaGetSymbolAddress((void**)&pacc, g_pacc);
    cudaGetSymbolAddress((void**)&pmv,  g_pm);
    cudaGetSymbolAddress((void**)&plv,  g_pl);
    cudaGetSymbolAddress((void**)&xh, g_xh);  cudaGetSymbolAddress((void**)&xl, g_xl);
    cudaGetSymbolAddress((void**)&ah, g_ah);  cudaGetSymbolAddress((void**)&al, g_al);
    cudaGetSymbolAddress((void**)&fh, g_fh);  cudaGetSymbolAddress((void**)&fl, g_fl);
    cudaGetSymbolAddress((void**)&qh, w_qkvh); cudaGetSymbolAddress((void**)&ql, w_qkvl);
    cudaGetSymbolAddress((void**)&fch, w_fch); cudaGetSymbolAddress((void**)&fcl, w_fcl);
    cudaGetSymbolAddress((void**)&f1h, w_f1h); cudaGetSymbolAddress((void**)&f1l, w_f1l);
    cudaGetSymbolAddress((void**)&f2h, w_f2h); cudaGetSymbolAddress((void**)&f2l, w_f2l);
    cudaGetSymbolAddress((void**)&oh, w_oh);   cudaGetSymbolAddress((void**)&ol, w_ol);

    cvt_kernel<<<2048, 256>>>(qkv_w, qh, ql, LL*DQKV*DD/4);
    cvt_kernel<<<1024, 256>>>(fc_w,  fch, fcl, LL*DD*DD/4);
    cvt_kernel<<<2048, 256>>>(ff1_w, f1h, f1l, LL*DFF*DD/4);
    cvt_kernel<<<2048, 256>>>(ff2_w, f2h, f2l, LL*DD*DFF/4);
    cvt_kernel<<<4096, 256>>>(out_w, oh, ol, VV*DD/4);

    embed_kernel<<<NTOK, 256>>>(x, tok_emb, pos_emb);

    for (int l = 0; l < LL; l++) {
        const __nv_bfloat16* wqh = qh + (size_t)l * DQKV * DD;
        const __nv_bfloat16* wql = ql + (size_t)l * DQKV * DD;
        const __nv_bfloat16* wph = fch + (size_t)l * DD * DD;
        const __nv_bfloat16* wpl = fcl + (size_t)l * DD * DD;
        const __nv_bfloat16* w1h = f1h + (size_t)l * DFF * DD;
        const __nv_bfloat16* w1l = f1l + (size_t)l * DFF * DD;
        const __nv_bfloat16* w2h = f2h + (size_t)l * DD * DFF;
        const __nv_bfloat16* w2l = f2l + (size_t)l * DD * DFF;

        ln_kernel<<<NTOK, 256>>>(h, ln1_s + (size_t)l*DD, ln1_b + (size_t)l*DD, xh, xl);
        mm_kernel<0><<<dim3(NTOK/128, DQKV/64), 256, GEMM_SMEM>>>(
            xh, xl, wqh, wql, nullptr, qkvb, nullptr, nullptr, DQKV, DD);
        attn_kernel<<<dim3(TT/64, BB*HH, NSPLIT), 64>>>(qkvb, pacc, pmv, plv);
        attn_merge<<<NTOK*HH, 64>>>(pacc, pmv, plv, ah, al);
        mm_kernel<2><<<dim3(NTOK/128, DD/64), 256, GEMM_SMEM>>>(
            ah, al, wph, wpl, fc_b + (size_t)l*DD, h, nullptr, nullptr, DD, DD);
        ln_kernel<<<NTOK, 256>>>(h, ln2_s + (size_t)l*DD, ln2_b + (size_t)l*DD, xh, xl);
        mm_kernel<3><<<dim3(NTOK/128, DFF/64), 256, GEMM_SMEM>>>(
            xh, xl, w1h, w1l, ff1_b + (size_t)l*DFF, nullptr, fh, fl, DFF, DD);
        mm_kernel<2><<<dim3(NTOK/128, DD/64), 256, GEMM_SMEM>>>(
            fh, fl, w2h, w2l, ff2_b + (size_t)l*DD, h, nullptr, nullptr, DD, DFF);
    }

    ln_kernel<<<NTOK, 256>>>(h, lnf_s, lnf_b, xh, xl);
    mm_kernel<1><<<dim3(NTOK/128, VV/64), 256, GEMM_SMEM>>>(
        xh, xl, oh, ol, out_b, logits, nullptr, nullptr, VV, DD);
}

// round 11
// speedup vs baseline: 1.6408x; 1.0270x over previous
#include <cuda_runtime.h>
#include <cuda_bf16.h>
#include <math.h>
#include <stdint.h>

// ---------------- Problem constants ----------------
#define BB    4
#define TT    1024
#define NTOK  (BB*TT)
#define DD    768
#define HH    12
#define HD    64
#define LL    6
#define VV    32000
#define DFF   3072
#define DQKV  2304
#define EPS   1e-5f
#define NSPLIT 8

// ---------------- Static device buffers ------------
__device__ float g_h   [NTOK * DD];     // residual stream (fp32)
__device__ float g_qkv [NTOK * DQKV];   // qkv projections (fp32)
__device__ __nv_bfloat16 g_xh[NTOK*DD],  g_xl[NTOK*DD];    // LN out hi/lo
__device__ __nv_bfloat16 g_ah[NTOK*DD],  g_al[NTOK*DD];    // attn out hi/lo
__device__ __nv_bfloat16 g_fh[NTOK*DFF], g_fl[NTOK*DFF];   // relu out hi/lo
// flash-decoding partials
__device__ float g_pacc[(size_t)NSPLIT * NTOK * DD];
__device__ float g_pm  [(size_t)NSPLIT * NTOK * HH];
__device__ float g_pl  [(size_t)NSPLIT * NTOK * HH];
// bf16 hi/lo weight copies
__device__ __nv_bfloat16 w_qkvh[LL*DQKV*DD], w_qkvl[LL*DQKV*DD];
__device__ __nv_bfloat16 w_fch [LL*DD*DD],   w_fcl [LL*DD*DD];
__device__ __nv_bfloat16 w_f1h [LL*DFF*DD],  w_f1l [LL*DFF*DD];
__device__ __nv_bfloat16 w_f2h [LL*DD*DFF],  w_f2l [LL*DD*DFF];
__device__ __nv_bfloat16 w_oh  [VV*DD],      w_ol  [VV*DD];

// ---------------- PTX helpers (arch-generic only) ---
__device__ __forceinline__ uint32_t smem_to_u32(const void* p) {
    uint32_t a;
    asm("{ .reg .u64 t; cvta.to.shared.u64 t, %1; cvt.u32.u64 %0, t; }"
        : "=r"(a) : "l"(p));
    return a;
}
#define CP_ASYNC16(dst, src) \
    asm volatile("cp.async.cg.shared.global [%0], [%1], 16;" :: "r"(dst), "l"(src))
#define CP_COMMIT asm volatile("cp.async.commit_group;" ::: "memory")
#define CP_WAIT1  asm volatile("cp.async.wait_group 1;" ::: "memory")
#define CP_WAIT0  asm volatile("cp.async.wait_group 0;" ::: "memory")

__device__ __forceinline__ void ldsm4(uint32_t* r, uint32_t addr) {
    asm volatile("ldmatrix.sync.aligned.m8n8.x4.shared.b16 {%0,%1,%2,%3}, [%4];"
        : "=r"(r[0]), "=r"(r[1]), "=r"(r[2]), "=r"(r[3]) : "r"(addr));
}
__device__ __forceinline__ void ldsm2(uint32_t* r, uint32_t addr) {
    asm volatile("ldmatrix.sync.aligned.m8n8.x2.shared.b16 {%0,%1}, [%2];"
        : "=r"(r[0]), "=r"(r[1]) : "r"(addr));
}
__device__ __forceinline__ void mma_bf16(float* d, const uint32_t* a, const uint32_t* b) {
    asm volatile("mma.sync.aligned.m16n8k16.row.col.f32.bf16.bf16.f32 "
        "{%0,%1,%2,%3}, {%4,%5,%6,%7}, {%8,%9}, {%0,%1,%2,%3};"
        : "+f"(d[0]), "+f"(d[1]), "+f"(d[2]), "+f"(d[3])
        : "r"(a[0]), "r"(a[1]), "r"(a[2]), "r"(a[3]), "r"(b[0]), "r"(b[1]));
}

__device__ __forceinline__ float dot4(const float4& a, const float4& b) {
    return fmaf(a.x, b.x, fmaf(a.y, b.y, fmaf(a.z, b.z, a.w * b.w)));
}

// ---------------- Embedding ------------------------
__global__ void embed_kernel(const int* __restrict__ x,
                             const float* __restrict__ tok_emb,
                             const float* __restrict__ pos_emb) {
    int row = blockIdx.x;
    int t   = row % TT;
    int id  = x[row];
    const float* te = tok_emb + (size_t)id * DD;
    const float* pe = pos_emb + (size_t)t  * DD;
    float* out = g_h + (size_t)row * DD;
    for (int i = threadIdx.x; i < DD; i += blockDim.x)
        out[i] = te[i] + pe[i];
}

// ---------------- fp32 -> bf16 hi/lo split ---------
__global__ void cvt_kernel(const float* __restrict__ s,
                           __nv_bfloat16* __restrict__ hi,
                           __nv_bfloat16* __restrict__ lo, int n4) {
    int i = blockIdx.x * blockDim.x + threadIdx.x;
    int stride = gridDim.x * blockDim.x;
    for (; i < n4; i += stride) {
        float4 v = ((const float4*)s)[i];
        __nv_bfloat16 h0 = __float2bfloat16(v.x);
        __nv_bfloat16 h1 = __float2bfloat16(v.y);
        __nv_bfloat16 h2 = __float2bfloat16(v.z);
        __nv_bfloat16 h3 = __float2bfloat16(v.w);
        __nv_bfloat16 l0 = __float2bfloat16(v.x - __bfloat162float(h0));
        __nv_bfloat16 l1 = __float2bfloat16(v.y - __bfloat162float(h1));
        __nv_bfloat16 l2 = __float2bfloat16(v.z - __bfloat162float(h2));
        __nv_bfloat16 l3 = __float2bfloat16(v.w - __bfloat162float(h3));
        __nv_bfloat162* ph = (__nv_bfloat162*)hi + i*2;
        __nv_bfloat162* pl = (__nv_bfloat162*)lo + i*2;
        ph[0] = __nv_bfloat162(h0, h1); ph[1] = __nv_bfloat162(h2, h3);
        pl[0] = __nv_bfloat162(l0, l1); pl[1] = __nv_bfloat162(l2, l3);
    }
}

// ---------------- LayerNorm -> bf16 hi/lo ----------
__device__ __forceinline__ float block_reduce_sum(float v, float* red) {
    int lane = threadIdx.x & 31, wid = threadIdx.x >> 5;
    #pragma unroll
    for (int o = 16; o > 0; o >>= 1) v += __shfl_xor_sync(0xffffffffu, v, o);
    if (lane == 0) red[wid] = v;
    __syncthreads();
    if (wid == 0) {
        float w = (lane < (blockDim.x >> 5)) ? red[lane] : 0.f;
        #pragma unroll
        for (int o = 4; o > 0; o >>= 1) w += __shfl_xor_sync(0xffffffffu, w, o);
        if (lane == 0) red[0] = w;
    }
    __syncthreads();
    float r = red[0];
    __syncthreads();
    return r;
}

__global__ void ln_kernel(const float* __restrict__ xin,
                          const float* __restrict__ sc,
                          const float* __restrict__ bi,
                          __nv_bfloat16* __restrict__ yh,
                          __nv_bfloat16* __restrict__ yl) {
    __shared__ float red[32];
    int row = blockIdx.x;
    const float* xr = xin + (size_t)row * DD;
    float xv[3];
    float s = 0.f;
    #pragma unroll
    for (int i = 0; i < 3; i++) { xv[i] = xr[threadIdx.x + i*256]; s += xv[i]; }
    float mean = block_reduce_sum(s, red) * (1.0f / DD);
    float vs = 0.f;
    #pragma unroll
    for (int i = 0; i < 3; i++) { float d = xv[i] - mean; vs += d * d; }
    float var = block_reduce_sum(vs, red) * (1.0f / DD);
    float rstd = rsqrtf(var + EPS);
    #pragma unroll
    for (int i = 0; i < 3; i++) {
        int c = threadIdx.x + i*256;
        float v = (xv[i] - mean) * rstd * sc[c] + bi[c];
        __nv_bfloat16 h = __float2bfloat16(v);
        yh[(size_t)row*DD + c] = h;
        yl[(size_t)row*DD + c] = __float2bfloat16(v - __bfloat162float(h));
    }
}

// =============== 128x64 HMMA GEMM, 2 CTAs/SM (validated) ===================
#define KC         64
#define S_AH       0
#define S_AL       16384
#define S_WH       32768
#define S_WL       40960
#define STG_B      49152
#define GEMM_SMEM  (2*STG_B)

template<int OP>
__global__ __launch_bounds__(256, 2)
void mm_kernel(const __nv_bfloat16* __restrict__ Ah, const __nv_bfloat16* __restrict__ Al,
               const __nv_bfloat16* __restrict__ Wh, const __nv_bfloat16* __restrict__ Wl,
               const float* __restrict__ bias, float* __restrict__ C,
               __nv_bfloat16* __restrict__ Oh, __nv_bfloat16* __restrict__ Ol,
               int N, int K) {
    extern __shared__ char smem[];
    const uint32_t sb = smem_to_u32(smem);
    int tid = threadIdx.x, lane = tid & 31, warp = tid >> 5;
    int wm = warp >> 1;
    int wn = warp & 1;
    int bm = blockIdx.x * 128, bn = blockIdx.y * 64;

    float acc[2][4][4];
    #pragma unroll
    for (int i = 0; i < 2; i++)
        #pragma unroll
        for (int j = 0; j < 4; j++)
            #pragma unroll
            for (int k = 0; k < 4; k++) acc[i][j][k] = 0.f;

    int arow = tid >> 1;
    int ac0  = (tid & 1) * 4;
    const __nv_bfloat16* gA_h = Ah + (size_t)(bm + arow) * K + ac0 * 8;
    const __nv_bfloat16* gA_l = Al + (size_t)(bm + arow) * K + ac0 * 8;
    uint32_t asrow = (uint32_t)arow * 128;
    int arsw = arow & 7;
    int wrow = tid >> 2;
    int wc0  = (tid & 3) * 2;
    const __nv_bfloat16* gW_h = Wh + (size_t)(bn + wrow) * K + wc0 * 8;
    const __nv_bfloat16* gW_l = Wl + (size_t)(bn + wrow) * K + wc0 * 8;
    uint32_t wsrow = (uint32_t)wrow * 128;
    int wrsw = wrow & 7;

    int mat = lane >> 3, r8 = lane & 7;
    int a_kh = mat >> 1;
    uint32_t arowb[2]; int aswz[2];
    #pragma unroll
    for (int ti = 0; ti < 2; ti++) {
        int row = wm*32 + ti*16 + (mat & 1)*8 + r8;
        arowb[ti] = (uint32_t)row * 128;
        aswz[ti]  = row & 7;
    }
    int bl15 = lane & 15;
    int b_kh = bl15 >> 3;
    uint32_t browb[4]; int bswz[4];
    #pragma unroll
    for (int ni = 0; ni < 4; ni++) {
        int row = wn*32 + ni*8 + (bl15 & 7);
        browb[ni] = (uint32_t)row * 128;
        bswz[ni]  = row & 7;
    }

    const int nch = K / KC;
    {
        uint32_t st = sb;
        #pragma unroll
        for (int i = 0; i < 4; i++) {
            int c = ac0 + i;
            uint32_t soff = asrow + (uint32_t)((c ^ arsw) << 4);
            CP_ASYNC16(st + S_AH + soff, gA_h + i*8);
            CP_ASYNC16(st + S_AL + soff, gA_l + i*8);
        }
        #pragma unroll
        for (int i = 0; i < 2; i++) {
            int c = wc0 + i;
            uint32_t soff = wsrow + (uint32_t)((c ^ wrsw) << 4);
            CP_ASYNC16(st + S_WH + soff, gW_h + i*8);
            CP_ASYNC16(st + S_WL + soff, gW_l + i*8);
        }
        CP_COMMIT;
    }

    for (int ch = 0; ch < nch; ch++) {
        if (ch + 1 < nch) {
            uint32_t st = sb + ((ch + 1) & 1) * STG_B;
            int k0 = (ch + 1) * KC;
            #pragma unroll
            for (int i = 0; i < 4; i++) {
                int c = ac0 + i;
                uint32_t soff = asrow + (uint32_t)((c ^ arsw) << 4);
                CP_ASYNC16(st + S_AH + soff, gA_h + k0 + i*8);
                CP_ASYNC16(st + S_AL + soff, gA_l + k0 + i*8);
            }
            #pragma unroll
            for (int i = 0; i < 2; i++) {
                int c = wc0 + i;
                uint32_t soff = wsrow + (uint32_t)((c ^ wrsw) << 4);
                CP_ASYNC16(st + S_WH + soff, gW_h + k0 + i*8);
                CP_ASYNC16(st + S_WL + soff, gW_l + k0 + i*8);
            }
            CP_COMMIT;
            CP_WAIT1;
        } else {
            CP_WAIT0;
        }
        __syncthreads();

        uint32_t stg = sb + (ch & 1) * STG_B;
        #pragma unroll
        for (int ks = 0; ks < 4; ks++) {
            uint32_t ahf[2][4], alf[2][4];
            #pragma unroll
            for (int ti = 0; ti < 2; ti++) {
                uint32_t off = arowb[ti] + (uint32_t)((((ks << 1) | a_kh) ^ aswz[ti]) << 4);
                ldsm4(ahf[ti], stg + S_AH + off);
                ldsm4(alf[ti], stg + S_AL + off);
            }
            uint32_t bhf[4][2], blf[4][2];
            #pragma unroll
            for (int ni = 0; ni < 4; ni++) {
                uint32_t off = browb[ni] + (uint32_t)((((ks << 1) | b_kh) ^ bswz[ni]) << 4);
                ldsm2(bhf[ni], stg + S_WH + off);
                ldsm2(blf[ni], stg + S_WL + off);
            }
            #pragma unroll
            for (int ti = 0; ti < 2; ti++)
                #pragma unroll
                for (int ni = 0; ni < 4; ni++) {
                    mma_bf16(acc[ti][ni], ahf[ti], bhf[ni]);
                    mma_bf16(acc[ti][ni], ahf[ti], blf[ni]);
                    mma_bf16(acc[ti][ni], alf[ti], bhf[ni]);
                }
        }
        __syncthreads();
    }

    int lr = lane >> 2, lc = (lane & 3) * 2;
    #pragma unroll
    for (int ti = 0; ti < 2; ti++) {
        #pragma unroll
        for (int ni = 0; ni < 4; ni++) {
            int grow = bm + wm*32 + ti*16 + lr;
            int gcol = bn + wn*32 + ni*8 + lc;
            #pragma unroll
            for (int half = 0; half < 2; half++) {
                int r = grow + half*8;
                size_t off = (size_t)r * N + gcol;
                float v0 = acc[ti][ni][half*2 + 0];
                float v1 = acc[ti][ni][half*2 + 1];
                if (OP == 0) {
                    *(float2*)&C[off] = make_float2(v0, v1);
                } else if (OP == 1) {
                    *(float2*)&C[off] = make_float2(v0 + bias[gcol], v1 + bias[gcol+1]);
                } else if (OP == 2) {
                    float2 hcur = *(float2*)&C[off];
                    *(float2*)&C[off] = make_float2(v0 + bias[gcol]   + hcur.x,
                                                    v1 + bias[gcol+1] + hcur.y);
                } else {
                    float f0 = fmaxf(v0 + bias[gcol],   0.f);
                    float f1 = fmaxf(v1 + bias[gcol+1], 0.f);
                    __nv_bfloat16 h0 = __float2bfloat16(f0);
                    __nv_bfloat16 h1 = __float2bfloat16(f1);
                    *(__nv_bfloat162*)&Oh[off] = __nv_bfloat162(h0, h1);
                    __nv_bfloat16 l0 = __float2bfloat16(f0 - __bfloat162float(h0));
                    __nv_bfloat16 l1 = __float2bfloat16(f1 - __bfloat162float(h1));
                    *(__nv_bfloat162*)&Ol[off] = __nv_bfloat162(l0, l1);
                }
            }
        }
    }
}

// =============== Causal attention: pair-split + KV-split (S=8) =============
// 128 threads = 64 queries; thread pair (2*qi, 2*qi+1) shares query qi,
// parity par owns interleaved float4 chunks c = 2t+par (t=0..7).
// Score combined via one shfl_xor(1) under a warp-uniform trip count.
__global__ __launch_bounds__(128)
void attn_kernel(const float* __restrict__ qkv,
                 float* __restrict__ pacc, float* __restrict__ pm,
                 float* __restrict__ pl) {
    __shared__ float4 Ks[1024];   // 64 rows x 16 float4
    __shared__ float4 Vs[1024];

    int bh = blockIdx.y;
    int b  = bh / HH, h = bh % HH;
    int qb = blockIdx.x;
    int sp = blockIdx.z;
    int tid = threadIdx.x;
    int qi  = tid >> 1;
    int par = tid & 1;
    int warp = tid >> 5;
    int q    = qb * 64 + qi;
    int tok  = b * TT + q;
    int qwmax = qb * 64 + warp * 16 + 15;   // warp covers 16 queries

    float4 a4[8];
    #pragma unroll
    for (int i = 0; i < 8; i++) a4[i] = make_float4(0.f, 0.f, 0.f, 0.f);
    float mmax = -1e30f, lsum = 0.f;

    if (sp <= qb) {
        float4 q4[8];
        const float4* qp = (const float4*)(qkv + (size_t)tok * DQKV + h * HD);
        #pragma unroll
        for (int t = 0; t < 8; t++) {
            q4[t] = qp[2*t + par];
            q4[t].x *= 0.125f; q4[t].y *= 0.125f; q4[t].z *= 0.125f; q4[t].w *= 0.125f;
        }

        for (int kt = sp; kt <= qb; kt += NSPLIT) {
            const float* kb = qkv + (size_t)(b*TT + kt*64) * DQKV + DD + h*HD;
            const float* vb = kb + DD;
            __syncthreads();
            #pragma unroll
            for (int c = 0; c < 8; c++) {
                int f = c * 128 + tid;            // flat float4 index
                int row = f >> 4, col = f & 15;
                Ks[f] = *(const float4*)(kb + (size_t)row * DQKV + col * 4);
                Vs[f] = *(const float4*)(vb + (size_t)row * DQKV + col * 4);
            }
            __syncthreads();

            int jm = qwmax - kt*64 + 1;           // warp-uniform, always >= 1
            if (jm > 64) jm = 64;
            for (int j = 0; j < jm; j++) {
                const float4* kr = &Ks[j * 16];
                float sA, sB, sC, sD;
                sA  = dot4(q4[0], kr[0 + par]);
                sB  = dot4(q4[1], kr[2 + par]);
                sC  = dot4(q4[2], kr[4 + par]);
                sD  = dot4(q4[3], kr[6 + par]);
                sA += dot4(q4[4], kr[8 + par]);
                sB += dot4(q4[5], kr[10 + par]);
                sC += dot4(q4[6], kr[12 + par]);
                sD += dot4(q4[7], kr[14 + par]);
                float s = (sA + sB) + (sC + sD);
                s += __shfl_xor_sync(0xffffffffu, s, 1);   // pair combine

                int rel = kt*64 + j;
                bool ok = (rel <= q);
                float p;
                if (ok && s > mmax) {
                    float corr = __expf(mmax - s);
                    #pragma unroll
                    for (int i = 0; i < 8; i++) {
                        a4[i].x *= corr; a4[i].y *= corr;
                        a4[i].z *= corr; a4[i].w *= corr;
                    }
                    lsum *= corr; mmax = s; p = 1.f;
                } else {
                    p = ok ? __expf(s - mmax) : 0.f;
                }
                lsum += p;

                const float4* vr = &Vs[j * 16];
                #pragma unroll
                for (int t = 0; t < 8; t++) {
                    float4 vv = vr[2*t + par];
                    a4[t].x = fmaf(p, vv.x, a4[t].x);
                    a4[t].y = fmaf(p, vv.y, a4[t].y);
                    a4[t].z = fmaf(p, vv.z, a4[t].z);
                    a4[t].w = fmaf(p, vv.w, a4[t].w);
                }
            }
        }
    }

    // store raw partials (thread writes its interleaved chunks)
    size_t ab = ((size_t)sp * NTOK + tok) * DD + h * HD;
    #pragma unroll
    for (int t = 0; t < 8; t++)
        *(float4*)&pacc[ab + (2*t + par) * 4] = a4[t];
    if (par == 0) {
        size_t mi = ((size_t)sp * NTOK + tok) * HH + h;
        pm[mi] = mmax;
        pl[mi] = lsum;
    }
}

// Merge NSPLIT partials -> bf16 hi/lo attention output.
__global__ __launch_bounds__(64)
void attn_merge(const float* __restrict__ pacc, const float* __restrict__ pm,
                const float* __restrict__ pl,
                __nv_bfloat16* __restrict__ oh, __nv_bfloat16* __restrict__ ol) {
    int tokh = blockIdx.x;
    int tok = tokh / HH, h = tokh % HH;
    int d = threadIdx.x;

    float m[NSPLIT], l[NSPLIT];
    float M = -1e30f;
    #pragma unroll
    for (int s = 0; s < NSPLIT; s++) {
        size_t mi = ((size_t)s * NTOK + tok) * HH + h;
        m[s] = pm[mi]; l[s] = pl[mi];
        M = fmaxf(M, m[s]);
    }
    float L = 0.f, w[NSPLIT];
    #pragma unroll
    for (int s = 0; s < NSPLIT; s++) {
        w[s] = __expf(m[s] - M);
        L = fmaf(l[s], w[s], L);
    }
    float v = 0.f;
    #pragma unroll
    for (int s = 0; s < NSPLIT; s++) {
        size_t ab = ((size_t)s * NTOK + tok) * DD + h * HD + d;
        v = fmaf(pacc[ab], w[s], v);
    }
    float f = v / L;
    size_t ob = (size_t)tok * DD + h * HD + d;
    __nv_bfloat16 hh = __float2bfloat16(f);
    oh[ob] = hh;
    ol[ob] = __float2bfloat16(f - __bfloat162float(hh));
}

// ---------------- Driver ---------------------------
extern "C" void kernel_launch(void* const* d_in, const int* in_sizes, int n_in,
                              void* d_out, int out_size) {
    (void)in_sizes; (void)n_in; (void)out_size;
    const int*   x       = (const int*)  d_in[0];
    const float* tok_emb = (const float*)d_in[1];
    const float* pos_emb = (const float*)d_in[2];
    const float* qkv_w   = (const float*)d_in[3];
    const float* fc_w    = (const float*)d_in[4];
    const float* fc_b    = (const float*)d_in[5];
    const float* ln1_s   = (const float*)d_in[6];
    const float* ln1_b   = (const float*)d_in[7];
    const float* ln2_s   = (const float*)d_in[8];
    const float* ln2_b   = (const float*)d_in[9];
    const float* ff1_w   = (const float*)d_in[10];
    const float* ff1_b   = (const float*)d_in[11];
    const float* ff2_w   = (const float*)d_in[12];
    const float* ff2_b   = (const float*)d_in[13];
    const float* lnf_s   = (const float*)d_in[14];
    const float* lnf_b   = (const float*)d_in[15];
    const float* out_w   = (const float*)d_in[16];
    const float* out_b   = (const float*)d_in[17];
    float* logits = (float*)d_out;

    cudaFuncSetAttribute(mm_kernel<0>, cudaFuncAttributeMaxDynamicSharedMemorySize, GEMM_SMEM);
    cudaFuncSetAttribute(mm_kernel<1>, cudaFuncAttributeMaxDynamicSharedMemorySize, GEMM_SMEM);
    cudaFuncSetAttribute(mm_kernel<2>, cudaFuncAttributeMaxDynamicSharedMemorySize, GEMM_SMEM);
    cudaFuncSetAttribute(mm_kernel<3>, cudaFuncAttributeMaxDynamicSharedMemorySize, GEMM_SMEM);

    float *h, *qkvb, *pacc, *pmv, *plv;
    __nv_bfloat16 *xh, *xl, *ah, *al, *fh, *fl;
    __nv_bfloat16 *qh, *ql, *fch, *fcl, *f1h, *f1l, *f2h, *f2l, *oh, *ol;
    cudaGetSymbolAddress((void**)&h,    g_h);
    cudaGetSymbolAddress((void**)&qkvb, g_qkv);
    cudaGetSymbolAddress((void**)&pacc, g_pacc);
    cudaGetSymbolAddress((void**)&pmv,  g_pm);
    cudaGetSymbolAddress((void**)&plv,  g_pl);
    cudaGetSymbolAddress((void**)&xh, g_xh);  cudaGetSymbolAddress((void**)&xl, g_xl);
    cudaGetSymbolAddress((void**)&ah, g_ah);  cudaGetSymbolAddress((void**)&al, g_al);
    cudaGetSymbolAddress((void**)&fh, g_fh);  cudaGetSymbolAddress((void**)&fl, g_fl);
    cudaGetSymbolAddress((void**)&qh, w_qkvh); cudaGetSymbolAddress((void**)&ql, w_qkvl);
    cudaGetSymbolAddress((void**)&fch, w_fch); cudaGetSymbolAddress((void**)&fcl, w_fcl);
    cudaGetSymbolAddress((void**)&f1h, w_f1h); cudaGetSymbolAddress((void**)&f1l, w_f1l);
    cudaGetSymbolAddress((void**)&f2h, w_f2h); cudaGetSymbolAddress((void**)&f2l, w_f2l);
    cudaGetSymbolAddress((void**)&oh, w_oh);   cudaGetSymbolAddress((void**)&ol, w_ol);

    cvt_kernel<<<2048, 256>>>(qkv_w, qh, ql, LL*DQKV*DD/4);
    cvt_kernel<<<1024, 256>>>(fc_w,  fch, fcl, LL*DD*DD/4);
    cvt_kernel<<<2048, 256>>>(ff1_w, f1h, f1l, LL*DFF*DD/4);
    cvt_kernel<<<2048, 256>>>(ff2_w, f2h, f2l, LL*DD*DFF/4);
    cvt_kernel<<<4096, 256>>>(out_w, oh, ol, VV*DD/4);

    embed_kernel<<<NTOK, 256>>>(x, tok_emb, pos_emb);

    for (int l = 0; l < LL; l++) {
        const __nv_bfloat16* wqh = qh + (size_t)l * DQKV * DD;
        const __nv_bfloat16* wql = ql + (size_t)l * DQKV * DD;
        const __nv_bfloat16* wph = fch + (size_t)l * DD * DD;
        const __nv_bfloat16* wpl = fcl + (size_t)l * DD * DD;
        const __nv_bfloat16* w1h = f1h + (size_t)l * DFF * DD;
        const __nv_bfloat16* w1l = f1l + (size_t)l * DFF * DD;
        const __nv_bfloat16* w2h = f2h + (size_t)l * DD * DFF;
        const __nv_bfloat16* w2l = f2l + (size_t)l * DD * DFF;

        ln_kernel<<<NTOK, 256>>>(h, ln1_s + (size_t)l*DD, ln1_b + (size_t)l*DD, xh, xl);
        mm_kernel<0><<<dim3(NTOK/128, DQKV/64), 256, GEMM_SMEM>>>(
            xh, xl, wqh, wql, nullptr, qkvb, nullptr, nullptr, DQKV, DD);
        attn_kernel<<<dim3(TT/64, BB*HH, NSPLIT), 128>>>(qkvb, pacc, pmv, plv);
        attn_merge<<<NTOK*HH, 64>>>(pacc, pmv, plv, ah, al);
        mm_kernel<2><<<dim3(NTOK/128, DD/64), 256, GEMM_SMEM>>>(
            ah, al, wph, wpl, fc_b + (size_t)l*DD, h, nullptr, nullptr, DD, DD);
        ln_kernel<<<NTOK, 256>>>(h, ln2_s + (size_t)l*DD, ln2_b + (size_t)l*DD, xh, xl);
        mm_kernel<3><<<dim3(NTOK/128, DFF/64), 256, GEMM_SMEM>>>(
            xh, xl, w1h, w1l, ff1_b + (size_t)l*DFF, nullptr, fh, fl, DFF, DD);
        mm_kernel<2><<<dim3(NTOK/128, DD/64), 256, GEMM_SMEM>>>(
            fh, fl, w2h, w2l, ff2_b + (size_t)l*DD, h, nullptr, nullptr, DD, DFF);
    }

    ln_kernel<<<NTOK, 256>>>(h, lnf_s, lnf_b, xh, xl);
    mm_kernel<1><<<dim3(NTOK/128, VV/64), 256, GEMM_SMEM>>>(
        xh, xl, oh, ol, out_b, logits, nullptr, nullptr, VV, DD);
}